// round 7
// baseline (speedup 1.0000x reference)
#include <cuda_runtime.h>
#include <cuda_bf16.h>
#include <math.h>
#include <stdint.h>

#define Bn   32
#define Sn   512
#define Dn   1024
#define Hn   16
#define DKn  64
#define BH   (Bn*Hn)                 // 512
#define Mtot (Bn*Sn)                 // 16384
#define CTX_ELEMS (Bn*Sn*Dn)         // 16,777,216
#define ATT_ELEMS ((size_t)Bn*Hn*Sn*Sn) // 134,217,728

// Scratch (allocation-free per harness rules)
__device__ float g_v[CTX_ELEMS];
__device__ float g_attn_fallback[ATT_ELEMS];
// bf16 hi/lo splits
__device__ __nv_bfloat16 g_xb0[CTX_ELEMS];
__device__ __nv_bfloat16 g_xb1[CTX_ELEMS];
__device__ __nv_bfloat16 g_wb0[3*Dn*Dn];
__device__ __nv_bfloat16 g_wb1[3*Dn*Dn];
__device__ __nv_bfloat16 g_qb0[CTX_ELEMS];
__device__ __nv_bfloat16 g_qb1[CTX_ELEMS];
__device__ __nv_bfloat16 g_kb0[CTX_ELEMS];
__device__ __nv_bfloat16 g_kb1[CTX_ELEMS];
__device__ __nv_bfloat16 g_vt0[CTX_ELEMS];   // V^T: [bh][dk=64][s=512]
__device__ __nv_bfloat16 g_vt1[CTX_ELEMS];

// ---------------- mma.sync bf16 (non-'a' tensor path, works on sm_103) -----
__device__ __forceinline__ void mma_bf16(float4& d, const uint32_t* a,
                                         uint32_t b0, uint32_t b1) {
    asm volatile(
        "mma.sync.aligned.m16n8k16.row.col.f32.bf16.bf16.f32 "
        "{%0,%1,%2,%3},{%4,%5,%6,%7},{%8,%9},{%0,%1,%2,%3};"
        : "+f"(d.x), "+f"(d.y), "+f"(d.z), "+f"(d.w)
        : "r"(a[0]), "r"(a[1]), "r"(a[2]), "r"(a[3]), "r"(b0), "r"(b1));
}

__device__ __forceinline__ void bsplit(float v, __nv_bfloat16& h, __nv_bfloat16& l) {
    h = __float2bfloat16(v);
    l = __float2bfloat16(v - __bfloat162float(h));
}
__device__ __forceinline__ uint32_t packbf(__nv_bfloat16 a, __nv_bfloat16 b) {
    __nv_bfloat162 t(a, b);
    return *(uint32_t*)&t;
}

// ---------------------------------------------------------------------------
// prep: bf16 hi/lo splits of X and the 3 weight matrices
// ---------------------------------------------------------------------------
__global__ __launch_bounds__(256) void prep_x_kernel(const float* __restrict__ X)
{
    size_t i = (size_t)blockIdx.x * 256 + threadIdx.x;
    float4 v = ((const float4*)X)[i];
    float f[4] = {v.x, v.y, v.z, v.w};
    __nv_bfloat16 b0[4], b1[4];
#pragma unroll
    for (int k = 0; k < 4; k++) bsplit(f[k], b0[k], b1[k]);
    ((uint32_t*)g_xb0)[i*2]   = packbf(b0[0], b0[1]);
    ((uint32_t*)g_xb0)[i*2+1] = packbf(b0[2], b0[3]);
    ((uint32_t*)g_xb1)[i*2]   = packbf(b1[0], b1[1]);
    ((uint32_t*)g_xb1)[i*2+1] = packbf(b1[2], b1[3]);
}

__global__ __launch_bounds__(256) void prep_w_kernel(
    const float* __restrict__ Wq, const float* __restrict__ Wk, const float* __restrict__ Wv)
{
    size_t i = (size_t)blockIdx.x * 256 + threadIdx.x;
    int z = (int)(i >> 18);
    const float* src = (z == 0) ? Wq : (z == 1) ? Wk : Wv;
    float4 v = ((const float4*)src)[i & 262143];
    float f[4] = {v.x, v.y, v.z, v.w};
    __nv_bfloat16 b0[4], b1[4];
#pragma unroll
    for (int k = 0; k < 4; k++) bsplit(f[k], b0[k], b1[k]);
    ((uint32_t*)g_wb0)[i*2]   = packbf(b0[0], b0[1]);
    ((uint32_t*)g_wb0)[i*2+1] = packbf(b0[2], b0[3]);
    ((uint32_t*)g_wb1)[i*2]   = packbf(b1[0], b1[1]);
    ((uint32_t*)g_wb1)[i*2+1] = packbf(b1[2], b1[3]);
}

// ---------------------------------------------------------------------------
// QKV projection via mma.sync bf16x3: C = X @ W^T + bias
// ---------------------------------------------------------------------------
#define SA 20   // smem row stride in words

__global__ __launch_bounds__(256, 2) void qkv_mma_kernel(
    const float* __restrict__ bq, const float* __restrict__ bk, const float* __restrict__ bv)
{
    __shared__ uint32_t As[2][128*SA];
    __shared__ uint32_t Bs[2][128*SA];

    const int tid  = threadIdx.x;
    const int wid  = tid >> 5;
    const int lane = tid & 31;
    const int gid  = lane >> 2;
    const int tig  = lane & 3;
    const int wm   = wid >> 1;
    const int wn   = wid & 1;
    const int z    = blockIdx.z;
    const int bm   = blockIdx.y * 128;
    const int bn   = blockIdx.x * 128;
    const size_t zoff = (size_t)z * Dn * Dn;

    const __nv_bfloat16* w0p = g_wb0 + zoff;
    const __nv_bfloat16* w1p = g_wb1 + zoff;

    const int r0 = tid >> 3;
    const int c4 = tid & 7;

    float4 acc[2][8];
#pragma unroll
    for (int mt = 0; mt < 2; mt++)
#pragma unroll
        for (int nt = 0; nt < 8; nt++) acc[mt][nt] = make_float4(0.f, 0.f, 0.f, 0.f);

    uint2 areg[4], breg[4];
    {
        const __nv_bfloat16* a = g_xb0 + (size_t)bm * Dn;
        const __nv_bfloat16* w = w0p   + (size_t)bn * Dn;
#pragma unroll
        for (int j = 0; j < 4; j++) {
            int row = r0 + j*32;
            areg[j] = *(const uint2*)(a + (size_t)row*Dn + c4*4);
            breg[j] = *(const uint2*)(w + (size_t)row*Dn + c4*4);
        }
#pragma unroll
        for (int j = 0; j < 4; j++) {
            int row = r0 + j*32;
            int wo = row*SA + c4*2;
            *(uint2*)&As[0][wo] = areg[j];
            *(uint2*)&Bs[0][wo] = breg[j];
        }
    }
    __syncthreads();

    for (int it = 0; it < 96; it++) {
        const int cur = it & 1;
        if (it + 1 < 96) {
            int p  = (it + 1) >> 5;
            int kc = ((it + 1) & 31) * 32;
            const __nv_bfloat16* a = ((p == 2) ? g_xb1 : g_xb0) + (size_t)bm * Dn + kc;
            const __nv_bfloat16* w = ((p == 1) ? w1p  : w0p  ) + (size_t)bn * Dn + kc;
#pragma unroll
            for (int j = 0; j < 4; j++) {
                int row = r0 + j*32;
                areg[j] = *(const uint2*)(a + (size_t)row*Dn + c4*4);
                breg[j] = *(const uint2*)(w + (size_t)row*Dn + c4*4);
            }
        }
#pragma unroll
        for (int s = 0; s < 2; s++) {
            uint32_t af[2][4];
#pragma unroll
            for (int mt = 0; mt < 2; mt++) {
                int base = (wm*32 + mt*16 + gid)*SA + s*8 + tig;
                af[mt][0] = As[cur][base];
                af[mt][1] = As[cur][base + 8*SA];
                af[mt][2] = As[cur][base + 4];
                af[mt][3] = As[cur][base + 8*SA + 4];
            }
#pragma unroll
            for (int nt = 0; nt < 8; nt++) {
                int nb = (wn*64 + nt*8 + gid)*SA + s*8 + tig;
                uint32_t b0 = Bs[cur][nb];
                uint32_t b1 = Bs[cur][nb + 4];
                mma_bf16(acc[0][nt], af[0], b0, b1);
                mma_bf16(acc[1][nt], af[1], b0, b1);
            }
        }
        if (it + 1 < 96) {
            const int nxt = (it + 1) & 1;
#pragma unroll
            for (int j = 0; j < 4; j++) {
                int row = r0 + j*32;
                int wo = row*SA + c4*2;
                *(uint2*)&As[nxt][wo] = areg[j];
                *(uint2*)&Bs[nxt][wo] = breg[j];
            }
            __syncthreads();
        }
    }

    const float* bias = (z == 0) ? bq : (z == 1) ? bk : bv;
    if (z == 2) {
#pragma unroll
        for (int mt = 0; mt < 2; mt++) {
            int rowa = bm + wm*32 + mt*16 + gid;
            int rowb = rowa + 8;
            int ba = rowa >> 9, sa = rowa & 511;
            int bb2 = rowb >> 9, sb = rowb & 511;
#pragma unroll
            for (int nt = 0; nt < 8; nt++) {
                int feat = bn + wn*64 + nt*8 + tig*2;
                int h = feat >> 6, dk = feat & 63;
                float2 bv2 = *(const float2*)&bias[feat];
                float2 v0 = make_float2(acc[mt][nt].x + bv2.x, acc[mt][nt].y + bv2.y);
                float2 v1 = make_float2(acc[mt][nt].z + bv2.x, acc[mt][nt].w + bv2.y);
                *(float2*)&g_v[((size_t)((ba *Hn + h)*Sn + sa))*DKn + dk] = v0;
                *(float2*)&g_v[((size_t)((bb2*Hn + h)*Sn + sb))*DKn + dk] = v1;
            }
        }
    } else {
        __nv_bfloat16* o0 = (z == 0) ? g_qb0 : g_kb0;
        __nv_bfloat16* o1 = (z == 0) ? g_qb1 : g_kb1;
#pragma unroll
        for (int mt = 0; mt < 2; mt++) {
            int rowa = bm + wm*32 + mt*16 + gid;
            int rowb = rowa + 8;
            int ba = rowa >> 9, sa = rowa & 511;
            int bb2 = rowb >> 9, sb = rowb & 511;
#pragma unroll
            for (int nt = 0; nt < 8; nt++) {
                int feat = bn + wn*64 + nt*8 + tig*2;
                int h = feat >> 6, dk = feat & 63;
                float2 bv2 = *(const float2*)&bias[feat];
                float vx = acc[mt][nt].x + bv2.x, vy = acc[mt][nt].y + bv2.y;
                float vz = acc[mt][nt].z + bv2.x, vw = acc[mt][nt].w + bv2.y;
                __nv_bfloat16 hx,lx,hy,ly,hz,lz,hw,lw;
                bsplit(vx,hx,lx); bsplit(vy,hy,ly); bsplit(vz,hz,lz); bsplit(vw,hw,lw);
                size_t ia = ((size_t)((ba *Hn + h)*Sn + sa))*DKn + dk;
                size_t ib = ((size_t)((bb2*Hn + h)*Sn + sb))*DKn + dk;
                *(uint32_t*)&o0[ia] = packbf(hx,hy);
                *(uint32_t*)&o1[ia] = packbf(lx,ly);
                *(uint32_t*)&o0[ib] = packbf(hz,hw);
                *(uint32_t*)&o1[ib] = packbf(lz,lw);
            }
        }
    }
}

// ---------------------------------------------------------------------------
// vtrans: g_v fp32 [bh][s][64] -> bf16 hi/lo V^T [bh][64][512]
// ---------------------------------------------------------------------------
__global__ __launch_bounds__(256) void vtrans_kernel()
{
    const int bh = blockIdx.y;
    const int s0 = blockIdx.x * 64;
    __shared__ float T[64][65];
    const int tid = threadIdx.x;
#pragma unroll
    for (int j = 0; j < 4; j++) {
        int f = tid + j*256;
        int row = f >> 4, cc = (f & 15) * 4;
        float4 v = *(const float4*)&g_v[((size_t)bh*Sn + s0 + row)*DKn + cc];
        T[row][cc] = v.x; T[row][cc+1] = v.y; T[row][cc+2] = v.z; T[row][cc+3] = v.w;
    }
    __syncthreads();
#pragma unroll
    for (int j = 0; j < 8; j++) {
        int g = tid + j*256;
        int dk = g >> 5, sc = (g & 31) * 2;
        float va = T[sc][dk], vb = T[sc+1][dk];
        __nv_bfloat16 ha,la,hb,lb;
        bsplit(va,ha,la); bsplit(vb,hb,lb);
        size_t idx = ((size_t)bh*DKn + dk)*Sn + s0 + sc;
        *(uint32_t*)&g_vt0[idx] = packbf(ha,hb);
        *(uint32_t*)&g_vt1[idx] = packbf(la,lb);
    }
}

// ---------------------------------------------------------------------------
// Fused attention kernel: per (bh, 64-q tile)
//   Phase A: scores mma over 4 k-tiles of 128 -> exp -> e kept as bf16 hi/lo
//            pairs in smem (mma-fragment layout); rowsums in registers.
//            Fully-masked k-tiles: write zeros to attn directly.
//   Phase B: write attn = e * inv once (normalized); av mma from smem e,
//            scale accumulator by inv in epilogue.
// 512 threads = 16 warps. smem ~185KB dynamic, occ 1.
// ---------------------------------------------------------------------------
#define RW   260   // eh/el row stride in words (512 k -> 256 words + 4 pad)
#define EH_OFF 0
#define EL_OFF (64*RW*4)                   // 66560
#define PA_OFF (2*64*RW*4)                 // 133120
#define QS0_OFF  PA_OFF                    // 64x36 words
#define QS1_OFF (PA_OFF +  9216)
#define KS0_OFF (PA_OFF + 18432)           // 128x36 words
#define KS1_OFF (PA_OFF + 36864)
#define VS_OFF   PA_OFF                    // phase B: 2buf x 2split x 64x20 words
#define RS_OFF  (PA_OFF + 55296)           // rsum 64x4 floats
#define INV_OFF (RS_OFF + 1024)            // invS 64 floats
#define FUSED_SMEM (INV_OFF + 256)         // 189,696 bytes

__global__ __launch_bounds__(512, 1) void attn_fused_kernel(
    const int* __restrict__ length, float* __restrict__ attn, float* __restrict__ ctx)
{
    extern __shared__ char smem[];
    uint32_t* eh  = (uint32_t*)(smem + EH_OFF);
    uint32_t* el  = (uint32_t*)(smem + EL_OFF);
    uint32_t* Qs0 = (uint32_t*)(smem + QS0_OFF);
    uint32_t* Qs1 = (uint32_t*)(smem + QS1_OFF);
    uint32_t* Ks0 = (uint32_t*)(smem + KS0_OFF);
    uint32_t* Ks1 = (uint32_t*)(smem + KS1_OFF);
    float*    rsum = (float*)(smem + RS_OFF);
    float*    invS = (float*)(smem + INV_OFF);

    const int tid  = threadIdx.x;
    const int wid  = tid >> 5;
    const int lane = tid & 31;
    const int gid  = lane >> 2;
    const int tig  = lane & 3;
    const int wm   = wid >> 2;    // 0..3: 16 q-rows each
    const int wn   = wid & 3;     // 0..3
    const int bh = blockIdx.y;
    const int b  = bh >> 4;
    const int h  = bh & 15;
    const int q0 = blockIdx.x * 64;

    const int len = length[b];
    float* attn_row0 = attn + ((size_t)bh*Sn + q0) * Sn;

    // ---- load Q splits once: 64 rows x 64 dk (stride 36 words) ------------
    {
        const __nv_bfloat16* qb0 = g_qb0 + ((size_t)bh*Sn + q0)*DKn;
        const __nv_bfloat16* qb1 = g_qb1 + ((size_t)bh*Sn + q0)*DKn;
#pragma unroll
        for (int j = 0; j < 2; j++) {
            int f = tid + j*512;          // 1024 uint2 sites
            int row = f >> 4, c2 = f & 15;
            uint2 v0 = *(const uint2*)(qb0 + (size_t)row*DKn + c2*4);
            uint2 v1 = *(const uint2*)(qb1 + (size_t)row*DKn + c2*4);
            *(uint2*)&Qs0[row*36 + c2*2] = v0;
            *(uint2*)&Qs1[row*36 + c2*2] = v1;
        }
    }

    // ---- Phase A: scores over 4 k-tiles ------------------------------------
    float s1 = 0.f, s2 = 0.f;   // rowsum partials for rows (wm*16+gid), (+8)
    const int r1 = wm*16 + gid;
    const int r2 = r1 + 8;

    for (int kt = 0; kt < 4; kt++) {
        const int k0 = kt * 128;
        if (k0 >= len) {
            // fully masked: write normalized zeros to attn, skip compute
            float4 z4 = make_float4(0.f, 0.f, 0.f, 0.f);
#pragma unroll
            for (int j = 0; j < 4; j++) {
                int f = tid + j*512;      // 2048 float4 sites
                int row = f >> 5, cc = (f & 31) * 4;
                *(float4*)(attn_row0 + (size_t)row*Sn + k0 + cc) = z4;
            }
            continue;
        }
        __syncthreads();   // previous kt's mma done (and Qs ready on kt==first)
        {
            const __nv_bfloat16* kb0 = g_kb0 + ((size_t)bh*Sn + k0)*DKn;
            const __nv_bfloat16* kb1 = g_kb1 + ((size_t)bh*Sn + k0)*DKn;
#pragma unroll
            for (int j = 0; j < 4; j++) {
                int f = tid + j*512;      // 2048 uint2 sites
                int row = f >> 4, c2 = f & 15;
                uint2 v0 = *(const uint2*)(kb0 + (size_t)row*DKn + c2*4);
                uint2 v1 = *(const uint2*)(kb1 + (size_t)row*DKn + c2*4);
                *(uint2*)&Ks0[row*36 + c2*2] = v0;
                *(uint2*)&Ks1[row*36 + c2*2] = v1;
            }
        }
        __syncthreads();

        float4 acc[4];
#pragma unroll
        for (int nt = 0; nt < 4; nt++) acc[nt] = make_float4(0.f, 0.f, 0.f, 0.f);

#pragma unroll
        for (int p = 0; p < 3; p++) {
            const uint32_t* Asrc = (p == 2) ? Qs1 : Qs0;
            const uint32_t* Bsrc = (p == 1) ? Ks1 : Ks0;
#pragma unroll
            for (int s = 0; s < 4; s++) {
                uint32_t af[4];
                int base = r1*36 + s*8 + tig;
                af[0] = Asrc[base];
                af[1] = Asrc[base + 8*36];
                af[2] = Asrc[base + 4];
                af[3] = Asrc[base + 8*36 + 4];
#pragma unroll
                for (int nt = 0; nt < 4; nt++) {
                    int nb = (wn*32 + nt*8 + gid)*36 + s*8 + tig;
                    mma_bf16(acc[nt], af, Bsrc[nb], Bsrc[nb + 4]);
                }
            }
        }

        // epilogue: exp + mask, store e splits to smem, accumulate rowsums
#pragma unroll
        for (int nt = 0; nt < 4; nt++) {
            int col = k0 + wn*32 + nt*8 + tig*2;
            float4 a = acc[nt];
            float ex = (col   < len) ? expf(a.x * 0.125f) : 0.f;
            float ey = (col+1 < len) ? expf(a.y * 0.125f) : 0.f;
            float ez = (col   < len) ? expf(a.z * 0.125f) : 0.f;
            float ew = (col+1 < len) ? expf(a.w * 0.125f) : 0.f;
            __nv_bfloat16 hx,lx,hy,ly,hz,lz,hw,lw;
            bsplit(ex,hx,lx); bsplit(ey,hy,ly); bsplit(ez,hz,lz); bsplit(ew,hw,lw);
            int w1 = r1*RW + (col >> 1);
            int w2 = r2*RW + (col >> 1);
            eh[w1] = packbf(hx,hy);  el[w1] = packbf(lx,ly);
            eh[w2] = packbf(hz,hw);  el[w2] = packbf(lz,lw);
            s1 += ex + ey;
            s2 += ez + ew;
        }
    }

    // ---- rowsum reduce -----------------------------------------------------
    s1 += __shfl_xor_sync(0xffffffffu, s1, 1);
    s1 += __shfl_xor_sync(0xffffffffu, s1, 2);
    s2 += __shfl_xor_sync(0xffffffffu, s2, 1);
    s2 += __shfl_xor_sync(0xffffffffu, s2, 2);
    if (tig == 0) {
        rsum[r1*4 + wn] = s1;
        rsum[r2*4 + wn] = s2;
    }
    __syncthreads();
    if (tid < 64) {
        float4 p = *(const float4*)&rsum[tid*4];
        invS[tid] = 1.0f / (p.x + p.y + p.z + p.w + 1e-8f);
    }
    __syncthreads();

    // ---- Phase B1: write normalized attn (single write) --------------------
    int kwb = (len + 127) & ~127; if (kwb > Sn) kwb = Sn;
    for (int t8 = 0; t8 < kwb; t8 += 128) {
#pragma unroll
        for (int j = 0; j < 4; j++) {
            int f = tid + j*512;          // 2048 float4 sites per 64x128 tile
            int row = f >> 5;
            int col = t8 + (f & 31) * 4;
            int wbase = row*RW + (col >> 1);
            uint32_t h0 = eh[wbase], h1 = eh[wbase+1];
            uint32_t l0 = el[wbase], l1 = el[wbase+1];
            __nv_bfloat162 H0 = *(__nv_bfloat162*)&h0, H1 = *(__nv_bfloat162*)&h1;
            __nv_bfloat162 L0 = *(__nv_bfloat162*)&l0, L1 = *(__nv_bfloat162*)&l1;
            float inv = invS[row];
            float4 o;
            o.x = (__bfloat162float(H0.x) + __bfloat162float(L0.x)) * inv;
            o.y = (__bfloat162float(H0.y) + __bfloat162float(L0.y)) * inv;
            o.z = (__bfloat162float(H1.x) + __bfloat162float(L1.x)) * inv;
            o.w = (__bfloat162float(H1.y) + __bfloat162float(L1.y)) * inv;
            *(float4*)(attn_row0 + (size_t)row*Sn + col) = o;
        }
    }

    // ---- Phase B2: av mma from smem e-splits --------------------------------
    uint32_t* Vs = (uint32_t*)(smem + VS_OFF);  // [buf][split][64 x 20 words]
    int kmax = (len + 31) & ~31; if (kmax > Sn) kmax = Sn;
    const __nv_bfloat16* vt0 = g_vt0 + (size_t)bh * DKn * Sn;
    const __nv_bfloat16* vt1 = g_vt1 + (size_t)bh * DKn * Sn;

    float4 accB[2];
    accB[0] = make_float4(0.f, 0.f, 0.f, 0.f);
    accB[1] = make_float4(0.f, 0.f, 0.f, 0.f);

    for (int kc = 0; kc < kmax; kc += 32) {
        __syncthreads();   // prev mma done reading Vs (first iter: B1 writes done too)
        {
            int f = tid;                  // 512 uint2 sites per split
            int row = f >> 3, c2 = f & 7;
            uint2 v0 = *(const uint2*)(vt0 + (size_t)row*Sn + kc + c2*4);
            uint2 v1 = *(const uint2*)(vt1 + (size_t)row*Sn + kc + c2*4);
            *(uint2*)&Vs[row*20 + c2*2]            = v0;
            *(uint2*)&Vs[64*20 + row*20 + c2*2]    = v1;
        }
        __syncthreads();
#pragma unroll
        for (int s = 0; s < 2; s++) {
            uint32_t af0[4], af1[4];
            int base = r1*RW + (kc >> 1) + s*8 + tig;
            af0[0] = eh[base];        af0[1] = eh[base + 8*RW];
            af0[2] = eh[base + 4];    af0[3] = eh[base + 8*RW + 4];
            af1[0] = el[base];        af1[1] = el[base + 8*RW];
            af1[2] = el[base + 4];    af1[3] = el[base + 8*RW + 4];
#pragma unroll
            for (int nt = 0; nt < 2; nt++) {
                int nb = (wn*16 + nt*8 + gid)*20 + s*8 + tig;
                uint32_t b00 = Vs[nb],         b01 = Vs[nb + 4];
                uint32_t b10 = Vs[64*20 + nb], b11 = Vs[64*20 + nb + 4];
                mma_bf16(accB[nt], af0, b00, b01);   // e_hi * v_hi
                mma_bf16(accB[nt], af0, b10, b11);   // e_hi * v_lo
                mma_bf16(accB[nt], af1, b00, b01);   // e_lo * v_hi
            }
        }
    }

    // ---- ctx epilogue: scale by inv ----------------------------------------
    float inv1 = invS[r1];
    float inv2 = invS[r2];
    int sa = q0 + r1;
    int sb = q0 + r2;
#pragma unroll
    for (int nt = 0; nt < 2; nt++) {
        int dk = wn*16 + nt*8 + tig*2;
        *(float2*)&ctx[((size_t)(b*Sn + sa))*Dn + h*DKn + dk] =
            make_float2(accB[nt].x * inv1, accB[nt].y * inv1);
        *(float2*)&ctx[((size_t)(b*Sn + sb))*Dn + h*DKn + dk] =
            make_float2(accB[nt].z * inv2, accB[nt].w * inv2);
    }
}

// ---------------------------------------------------------------------------
extern "C" void kernel_launch(void* const* d_in, const int* in_sizes, int n_in,
                              void* d_out, int out_size)
{
    const float* Q   = (const float*)d_in[0];
    const float* Wq  = (const float*)d_in[1];
    const float* bq  = (const float*)d_in[2];
    const float* Wk  = (const float*)d_in[3];
    const float* bk  = (const float*)d_in[4];
    const float* Wv  = (const float*)d_in[5];
    const float* bv  = (const float*)d_in[6];
    const int*   len = (const int*)d_in[7];

    float* ctx = (float*)d_out;
    float* attn;
    if ((size_t)out_size >= (size_t)CTX_ELEMS + ATT_ELEMS) {
        attn = ctx + CTX_ELEMS;   // tuple output: [context | attn]
    } else {
        void* p = nullptr;
        cudaGetSymbolAddress(&p, g_attn_fallback);
        attn = (float*)p;
    }

    cudaFuncSetAttribute(attn_fused_kernel,
                         cudaFuncAttributeMaxDynamicSharedMemorySize, FUSED_SMEM);

    // 0) bf16 hi/lo splits of inputs
    prep_x_kernel<<<dim3(CTX_ELEMS/4/256), 256>>>(Q);
    prep_w_kernel<<<dim3(3*Dn*Dn/4/256), 256>>>(Wq, Wk, Wv);
    // 1) QKV projections (tensor cores); q/k -> bf16 splits, v -> fp32
    qkv_mma_kernel<<<dim3(Dn/128, Mtot/128, 3), 256>>>(bq, bk, bv);
    // 1b) V^T bf16 splits
    vtrans_kernel<<<dim3(Sn/64, BH), 256>>>();
    // 2) fused scores + normalize + av (single attn write)
    attn_fused_kernel<<<dim3(Sn/64, BH), 512, FUSED_SMEM>>>(len, attn, ctx);
}

// round 8
// speedup vs baseline: 1.0415x; 1.0415x over previous
#include <cuda_runtime.h>
#include <cuda_bf16.h>
#include <math.h>
#include <stdint.h>

#define Bn   32
#define Sn   512
#define Dn   1024
#define Hn   16
#define DKn  64
#define BH   (Bn*Hn)                 // 512
#define Mtot (Bn*Sn)                 // 16384
#define CTX_ELEMS (Bn*Sn*Dn)         // 16,777,216
#define ATT_ELEMS ((size_t)Bn*Hn*Sn*Sn) // 134,217,728

// Scratch (allocation-free per harness rules)
__device__ float g_v[CTX_ELEMS];
__device__ float g_part[(size_t)BH*Sn*8];
__device__ float g_attn_fallback[ATT_ELEMS];
// q/k bf16 hi/lo splits + V^T splits (for attention mma)
__device__ __nv_bfloat16 g_qb0[CTX_ELEMS];
__device__ __nv_bfloat16 g_qb1[CTX_ELEMS];
__device__ __nv_bfloat16 g_kb0[CTX_ELEMS];
__device__ __nv_bfloat16 g_kb1[CTX_ELEMS];
__device__ __nv_bfloat16 g_vt0[CTX_ELEMS];   // V^T: [bh][dk=64][s=512]
__device__ __nv_bfloat16 g_vt1[CTX_ELEMS];
// int8 two-digit quantization of X and W (per-row scales)
__device__ int8_t g_xq0[CTX_ELEMS];
__device__ int8_t g_xq1[CTX_ELEMS];
__device__ int8_t g_wq0[3*Dn*Dn];
__device__ int8_t g_wq1[3*Dn*Dn];
__device__ float  g_sx[Mtot];        // s/127 per X row
__device__ float  g_tw[3*Dn];        // t/127 per W row (feature)

// ---------------- mma.sync helpers (non-'a' paths, work on sm_103) ---------
__device__ __forceinline__ void mma_bf16(float4& d, const uint32_t* a,
                                         uint32_t b0, uint32_t b1) {
    asm volatile(
        "mma.sync.aligned.m16n8k16.row.col.f32.bf16.bf16.f32 "
        "{%0,%1,%2,%3},{%4,%5,%6,%7},{%8,%9},{%0,%1,%2,%3};"
        : "+f"(d.x), "+f"(d.y), "+f"(d.z), "+f"(d.w)
        : "r"(a[0]), "r"(a[1]), "r"(a[2]), "r"(a[3]), "r"(b0), "r"(b1));
}
__device__ __forceinline__ void mma_s8(int* d, const uint32_t* a,
                                       uint32_t b0, uint32_t b1) {
    asm volatile(
        "mma.sync.aligned.m16n8k32.row.col.s32.s8.s8.s32 "
        "{%0,%1,%2,%3},{%4,%5,%6,%7},{%8,%9},{%0,%1,%2,%3};"
        : "+r"(d[0]), "+r"(d[1]), "+r"(d[2]), "+r"(d[3])
        : "r"(a[0]), "r"(a[1]), "r"(a[2]), "r"(a[3]), "r"(b0), "r"(b1));
}

__device__ __forceinline__ void bsplit(float v, __nv_bfloat16& h, __nv_bfloat16& l) {
    h = __float2bfloat16(v);
    l = __float2bfloat16(v - __bfloat162float(h));
}
__device__ __forceinline__ uint32_t packbf(__nv_bfloat16 a, __nv_bfloat16 b) {
    __nv_bfloat162 t(a, b);
    return *(uint32_t*)&t;
}

// ---------------------------------------------------------------------------
// prep: two-digit int8 quantization with per-row scale
// ---------------------------------------------------------------------------
__device__ __forceinline__ void quant_row(const float4 v, float inv,
                                          char4& c0, char4& c1) {
    int q0x = __float2int_rn(v.x*inv); int q1x = __float2int_rn((v.x*inv - q0x)*127.f);
    int q0y = __float2int_rn(v.y*inv); int q1y = __float2int_rn((v.y*inv - q0y)*127.f);
    int q0z = __float2int_rn(v.z*inv); int q1z = __float2int_rn((v.z*inv - q0z)*127.f);
    int q0w = __float2int_rn(v.w*inv); int q1w = __float2int_rn((v.w*inv - q0w)*127.f);
    c0 = make_char4((char)q0x, (char)q0y, (char)q0z, (char)q0w);
    c1 = make_char4((char)q1x, (char)q1y, (char)q1z, (char)q1w);
}

__global__ __launch_bounds__(256) void prep_xq_kernel(const float* __restrict__ X)
{
    const int r   = blockIdx.x;
    const int tid = threadIdx.x;
    const int lane = tid & 31;
    float4 v = ((const float4*)X)[(size_t)r*256 + tid];
    float m = fmaxf(fmaxf(fabsf(v.x), fabsf(v.y)), fmaxf(fabsf(v.z), fabsf(v.w)));
#pragma unroll
    for (int off = 16; off >= 1; off >>= 1)
        m = fmaxf(m, __shfl_xor_sync(0xffffffffu, m, off));
    __shared__ float wmax[8];
    if (lane == 0) wmax[tid >> 5] = m;
    __syncthreads();
    float s = wmax[0];
#pragma unroll
    for (int w = 1; w < 8; w++) s = fmaxf(s, wmax[w]);
    s = fmaxf(s, 1e-20f);
    float inv = 127.f / s;
    char4 c0, c1;
    quant_row(v, inv, c0, c1);
    ((char4*)g_xq0)[(size_t)r*256 + tid] = c0;
    ((char4*)g_xq1)[(size_t)r*256 + tid] = c1;
    if (tid == 0) g_sx[r] = s * (1.0f/127.0f);
}

__global__ __launch_bounds__(256) void prep_wq_kernel(
    const float* __restrict__ Wq, const float* __restrict__ Wk, const float* __restrict__ Wv)
{
    const int bid = blockIdx.x;          // z*1024 + row
    const int z   = bid >> 10;
    const int row = bid & 1023;
    const int tid = threadIdx.x;
    const int lane = tid & 31;
    const float* src = (z == 0) ? Wq : (z == 1) ? Wk : Wv;
    float4 v = ((const float4*)src)[(size_t)row*256 + tid];
    float m = fmaxf(fmaxf(fabsf(v.x), fabsf(v.y)), fmaxf(fabsf(v.z), fabsf(v.w)));
#pragma unroll
    for (int off = 16; off >= 1; off >>= 1)
        m = fmaxf(m, __shfl_xor_sync(0xffffffffu, m, off));
    __shared__ float wmax[8];
    if (lane == 0) wmax[tid >> 5] = m;
    __syncthreads();
    float s = wmax[0];
#pragma unroll
    for (int w = 1; w < 8; w++) s = fmaxf(s, wmax[w]);
    s = fmaxf(s, 1e-20f);
    float inv = 127.f / s;
    char4 c0, c1;
    quant_row(v, inv, c0, c1);
    ((char4*)g_wq0)[(size_t)bid*256 + tid] = c0;
    ((char4*)g_wq1)[(size_t)bid*256 + tid] = c1;
    if (tid == 0) g_tw[bid] = s * (1.0f/127.0f);
}

// ---------------------------------------------------------------------------
// QKV projection via int8 two-digit mma: C = X @ W^T + bias
// CTA tile 128x64, warp tile 32x32 (8 warps), K chunks of 32 (32 iters).
// acc_hi = q0*p0; acc_lo = q0*p1 + q1*p0. out = sx*tw*(hi + lo/127) + bias.
// q/k outputs -> bf16 hi/lo pairs; v -> fp32.
// ---------------------------------------------------------------------------
#define SB 12   // int8 smem row stride in words (32 int8 = 8 words + 4 pad)

__global__ __launch_bounds__(256, 2) void qkv_i8_kernel(
    const float* __restrict__ bq, const float* __restrict__ bk, const float* __restrict__ bv)
{
    __shared__ uint32_t Xs[2][2][128*SB];   // [buf][digit]
    __shared__ uint32_t Ws[2][2][64*SB];

    const int tid  = threadIdx.x;
    const int wid  = tid >> 5;
    const int lane = tid & 31;
    const int gid  = lane >> 2;
    const int tig  = lane & 3;
    const int wm   = wid >> 1;    // 0..3 (32 rows each)
    const int wn   = wid & 1;     // 0..1 (32 feats each)
    const int z    = blockIdx.z;
    const int bm   = blockIdx.y * 128;
    const int bn   = blockIdx.x * 64;

    const int8_t* xq[2] = { g_xq0 + (size_t)bm*Dn, g_xq1 + (size_t)bm*Dn };
    const size_t woff = (size_t)z*Dn*Dn + (size_t)bn*Dn;
    const int8_t* wq[2] = { g_wq0 + woff, g_wq1 + woff };

    const int rx = tid >> 2;      // 0..63
    const int cx = tid & 3;       // uint2 (8 int8) chunk within 32-col row

    int acch[2][4][4], accl[2][4][4];
#pragma unroll
    for (int mt = 0; mt < 2; mt++)
#pragma unroll
        for (int nt = 0; nt < 4; nt++)
#pragma unroll
            for (int r = 0; r < 4; r++) { acch[mt][nt][r] = 0; accl[mt][nt][r] = 0; }

    // load chunk 0
#pragma unroll
    for (int d = 0; d < 2; d++) {
#pragma unroll
        for (int j = 0; j < 2; j++) {
            int row = rx + 64*j;
            uint2 xv = *(const uint2*)(xq[d] + (size_t)row*Dn + cx*8);
            *(uint2*)&Xs[0][d][row*SB + cx*2] = xv;
        }
        uint2 wv = *(const uint2*)(wq[d] + (size_t)rx*Dn + cx*8);
        *(uint2*)&Ws[0][d][rx*SB + cx*2] = wv;
    }
    __syncthreads();

    for (int it = 0; it < 32; it++) {
        const int cur = it & 1;
        uint2 xr[2][2], wr[2];
        if (it + 1 < 32) {
            int kc = (it + 1) * 32;
#pragma unroll
            for (int d = 0; d < 2; d++) {
#pragma unroll
                for (int j = 0; j < 2; j++)
                    xr[d][j] = *(const uint2*)(xq[d] + (size_t)(rx + 64*j)*Dn + kc + cx*8);
                wr[d] = *(const uint2*)(wq[d] + (size_t)rx*Dn + kc + cx*8);
            }
        }
        // fragments + mma
        uint32_t af[2][2][4];
#pragma unroll
        for (int d = 0; d < 2; d++)
#pragma unroll
            for (int mt = 0; mt < 2; mt++) {
                int base = (wm*32 + mt*16 + gid)*SB + tig;
                af[d][mt][0] = Xs[cur][d][base];
                af[d][mt][1] = Xs[cur][d][base + 8*SB];
                af[d][mt][2] = Xs[cur][d][base + 4];
                af[d][mt][3] = Xs[cur][d][base + 8*SB + 4];
            }
#pragma unroll
        for (int nt = 0; nt < 4; nt++) {
            int nb = (wn*32 + nt*8 + gid)*SB + tig;
            uint32_t b00 = Ws[cur][0][nb], b01 = Ws[cur][0][nb + 4];
            uint32_t b10 = Ws[cur][1][nb], b11 = Ws[cur][1][nb + 4];
#pragma unroll
            for (int mt = 0; mt < 2; mt++) {
                mma_s8(acch[mt][nt], af[0][mt], b00, b01);   // q0*p0
                mma_s8(accl[mt][nt], af[0][mt], b10, b11);   // q0*p1
                mma_s8(accl[mt][nt], af[1][mt], b00, b01);   // q1*p0
            }
        }
        if (it + 1 < 32) {
            const int nxt = (it + 1) & 1;
#pragma unroll
            for (int d = 0; d < 2; d++) {
#pragma unroll
                for (int j = 0; j < 2; j++)
                    *(uint2*)&Xs[nxt][d][(rx + 64*j)*SB + cx*2] = xr[d][j];
                *(uint2*)&Ws[nxt][d][rx*SB + cx*2] = wr[d];
            }
            __syncthreads();
        }
    }

    // epilogue: combine digits, scale, add bias, store
    const float* bias = (z == 0) ? bq : (z == 1) ? bk : bv;
    const float c127 = 1.0f / 127.0f;
#pragma unroll
    for (int mt = 0; mt < 2; mt++) {
        int rowa = bm + wm*32 + mt*16 + gid;
        int rowb = rowa + 8;
        float ssa = g_sx[rowa];
        float ssb = g_sx[rowb];
        int ba = rowa >> 9, sa = rowa & 511;
        int bb2 = rowb >> 9, sb = rowb & 511;
#pragma unroll
        for (int nt = 0; nt < 4; nt++) {
            int feat = bn + wn*32 + nt*8 + tig*2;
            float2 twv = *(const float2*)&g_tw[z*Dn + feat];
            float2 bv2 = *(const float2*)&bias[feat];
            float vx = ssa*twv.x*((float)acch[mt][nt][0] + (float)accl[mt][nt][0]*c127) + bv2.x;
            float vy = ssa*twv.y*((float)acch[mt][nt][1] + (float)accl[mt][nt][1]*c127) + bv2.y;
            float vz = ssb*twv.x*((float)acch[mt][nt][2] + (float)accl[mt][nt][2]*c127) + bv2.x;
            float vw = ssb*twv.y*((float)acch[mt][nt][3] + (float)accl[mt][nt][3]*c127) + bv2.y;
            int h = feat >> 6, dk = feat & 63;
            if (z == 2) {
                *(float2*)&g_v[((size_t)((ba *Hn + h)*Sn + sa))*DKn + dk] = make_float2(vx, vy);
                *(float2*)&g_v[((size_t)((bb2*Hn + h)*Sn + sb))*DKn + dk] = make_float2(vz, vw);
            } else {
                __nv_bfloat16* o0 = (z == 0) ? g_qb0 : g_kb0;
                __nv_bfloat16* o1 = (z == 0) ? g_qb1 : g_kb1;
                __nv_bfloat16 hx,lx,hy,ly,hz,lz,hw,lw;
                bsplit(vx,hx,lx); bsplit(vy,hy,ly); bsplit(vz,hz,lz); bsplit(vw,hw,lw);
                size_t ia = ((size_t)((ba *Hn + h)*Sn + sa))*DKn + dk;
                size_t ib = ((size_t)((bb2*Hn + h)*Sn + sb))*DKn + dk;
                *(uint32_t*)&o0[ia] = packbf(hx,hy);
                *(uint32_t*)&o1[ia] = packbf(lx,ly);
                *(uint32_t*)&o0[ib] = packbf(hz,hw);
                *(uint32_t*)&o1[ib] = packbf(lz,lw);
            }
        }
    }
}

// ---------------------------------------------------------------------------
// vtrans: g_v fp32 [bh][s][64] -> bf16 hi/lo V^T [bh][64][512]
// ---------------------------------------------------------------------------
__global__ __launch_bounds__(256) void vtrans_kernel()
{
    const int bh = blockIdx.y;
    const int s0 = blockIdx.x * 64;
    __shared__ float T[64][65];
    const int tid = threadIdx.x;
#pragma unroll
    for (int j = 0; j < 4; j++) {
        int f = tid + j*256;
        int row = f >> 4, cc = (f & 15) * 4;
        float4 v = *(const float4*)&g_v[((size_t)bh*Sn + s0 + row)*DKn + cc];
        T[row][cc] = v.x; T[row][cc+1] = v.y; T[row][cc+2] = v.z; T[row][cc+3] = v.w;
    }
    __syncthreads();
#pragma unroll
    for (int j = 0; j < 8; j++) {
        int g = tid + j*256;
        int dk = g >> 5, sc = (g & 31) * 2;
        float va = T[sc][dk], vb = T[sc+1][dk];
        __nv_bfloat16 ha,la,hb,lb;
        bsplit(va,ha,la); bsplit(vb,hb,lb);
        size_t idx = ((size_t)bh*DKn + dk)*Sn + s0 + sc;
        *(uint32_t*)&g_vt0[idx] = packbf(ha,hb);
        *(uint32_t*)&g_vt1[idx] = packbf(la,lb);
    }
}

// ---------------------------------------------------------------------------
// scores via mma (R6 version): E = exp((q.k)/8)*mask, 128x128 tiles,
// masked tiles short-circuit to zero-fill. Fused row partials.
// ---------------------------------------------------------------------------
#define SA 20   // bf16 smem row stride in words

__global__ __launch_bounds__(256, 2) void scores_mma_kernel(
    const int* __restrict__ length, float* __restrict__ attn)
{
    __shared__ uint32_t As[2][128*SA];
    __shared__ uint32_t Bs[2][128*SA];

    const int tid  = threadIdx.x;
    const int wid  = tid >> 5;
    const int lane = tid & 31;
    const int gid  = lane >> 2;
    const int tig  = lane & 3;
    const int wm   = wid >> 1;
    const int wn   = wid & 1;
    const int bh = blockIdx.z;
    const int b  = bh >> 4;
    const int q0 = blockIdx.y * 128;
    const int k0 = blockIdx.x * 128;

    const int len = length[b];

    if (k0 >= len) {
        float4 z4 = make_float4(0.f, 0.f, 0.f, 0.f);
#pragma unroll
        for (int j = 0; j < 16; j++) {
            int f = tid + j*256;
            int row = f >> 5, cc = (f & 31) * 4;
            *(float4*)&attn[((size_t)bh*Sn + q0 + row)*Sn + k0 + cc] = z4;
        }
        if (tid < 128) {
            size_t pb = ((size_t)bh*Sn + q0 + tid)*8 + blockIdx.x*2;
            g_part[pb]     = 0.f;
            g_part[pb + 1] = 0.f;
        }
        return;
    }

    const int r0 = tid >> 3;
    const int c4 = tid & 7;

    const __nv_bfloat16* qs[2] = { g_qb0 + ((size_t)bh*Sn + q0)*DKn,
                                   g_qb1 + ((size_t)bh*Sn + q0)*DKn };
    const __nv_bfloat16* ks[2] = { g_kb0 + ((size_t)bh*Sn + k0)*DKn,
                                   g_kb1 + ((size_t)bh*Sn + k0)*DKn };
    const int pa[3] = {0, 0, 1};
    const int pb3[3] = {0, 1, 0};

    float4 acc[2][8];
#pragma unroll
    for (int mt = 0; mt < 2; mt++)
#pragma unroll
        for (int nt = 0; nt < 8; nt++) acc[mt][nt] = make_float4(0.f, 0.f, 0.f, 0.f);

    uint2 areg[4], breg[4];
    {
#pragma unroll
        for (int j = 0; j < 4; j++) {
            int row = r0 + j*32;
            areg[j] = *(const uint2*)(qs[0] + (size_t)row*DKn + c4*4);
            breg[j] = *(const uint2*)(ks[0] + (size_t)row*DKn + c4*4);
        }
#pragma unroll
        for (int j = 0; j < 4; j++) {
            int row = r0 + j*32;
            int wo = row*SA + c4*2;
            *(uint2*)&As[0][wo] = areg[j];
            *(uint2*)&Bs[0][wo] = breg[j];
        }
    }
    __syncthreads();

    for (int it = 0; it < 6; it++) {
        const int cur = it & 1;
        if (it + 1 < 6) {
            int p  = (it + 1) >> 1;
            int kc = ((it + 1) & 1) * 32;
            const __nv_bfloat16* a = qs[pa[p]] + kc;
            const __nv_bfloat16* w = ks[pb3[p]] + kc;
#pragma unroll
            for (int j = 0; j < 4; j++) {
                int row = r0 + j*32;
                areg[j] = *(const uint2*)(a + (size_t)row*DKn + c4*4);
                breg[j] = *(const uint2*)(w + (size_t)row*DKn + c4*4);
            }
        }
#pragma unroll
        for (int s = 0; s < 2; s++) {
            uint32_t af[2][4];
#pragma unroll
            for (int mt = 0; mt < 2; mt++) {
                int base = (wm*32 + mt*16 + gid)*SA + s*8 + tig;
                af[mt][0] = As[cur][base];
                af[mt][1] = As[cur][base + 8*SA];
                af[mt][2] = As[cur][base + 4];
                af[mt][3] = As[cur][base + 8*SA + 4];
            }
#pragma unroll
            for (int nt = 0; nt < 8; nt++) {
                int nb = (wn*64 + nt*8 + gid)*SA + s*8 + tig;
                uint32_t b0 = Bs[cur][nb];
                uint32_t b1 = Bs[cur][nb + 4];
                mma_bf16(acc[0][nt], af[0], b0, b1);
                mma_bf16(acc[1][nt], af[1], b0, b1);
            }
        }
        if (it + 1 < 6) {
            const int nxt = (it + 1) & 1;
#pragma unroll
            for (int j = 0; j < 4; j++) {
                int row = r0 + j*32;
                int wo = row*SA + c4*2;
                *(uint2*)&As[nxt][wo] = areg[j];
                *(uint2*)&Bs[nxt][wo] = breg[j];
            }
            __syncthreads();
        }
    }

#pragma unroll
    for (int mt = 0; mt < 2; mt++) {
        int sa = q0 + wm*32 + mt*16 + gid;
        int sb = sa + 8;
        float rpa = 0.f, rpb = 0.f;
#pragma unroll
        for (int nt = 0; nt < 8; nt++) {
            int kc0 = k0 + wn*64 + nt*8 + tig*2;
            float4 a = acc[mt][nt];
            float ex = (kc0   < len) ? expf(a.x * 0.125f) : 0.f;
            float ey = (kc0+1 < len) ? expf(a.y * 0.125f) : 0.f;
            float ez = (kc0   < len) ? expf(a.z * 0.125f) : 0.f;
            float ew = (kc0+1 < len) ? expf(a.w * 0.125f) : 0.f;
            *(float2*)&attn[((size_t)bh*Sn + sa)*Sn + kc0] = make_float2(ex, ey);
            *(float2*)&attn[((size_t)bh*Sn + sb)*Sn + kc0] = make_float2(ez, ew);
            rpa += ex + ey;
            rpb += ez + ew;
        }
        rpa += __shfl_xor_sync(0xffffffffu, rpa, 1);
        rpa += __shfl_xor_sync(0xffffffffu, rpa, 2);
        rpb += __shfl_xor_sync(0xffffffffu, rpb, 1);
        rpb += __shfl_xor_sync(0xffffffffu, rpb, 2);
        if (tig == 0) {
            g_part[((size_t)bh*Sn + sa)*8 + blockIdx.x*2 + wn] = rpa;
            g_part[((size_t)bh*Sn + sb)*8 + blockIdx.x*2 + wn] = rpb;
        }
    }
}

// ---------------------------------------------------------------------------
// av via mma (R6 version): ctx = (E @ V) * inv, K bounded by length[b],
// normalizes attn in place, rowsums folded in from partials.
// ---------------------------------------------------------------------------
__global__ __launch_bounds__(256, 2) void av_mma_kernel(
    const int* __restrict__ length, float* __restrict__ attn, float* __restrict__ ctx)
{
    __shared__ uint32_t As0[128*SA];
    __shared__ uint32_t As1[128*SA];
    __shared__ uint32_t Bs0[64*SA];
    __shared__ uint32_t Bs1[64*SA];
    __shared__ float invS[128];

    const int tid  = threadIdx.x;
    const int wid  = tid >> 5;
    const int lane = tid & 31;
    const int gid  = lane >> 2;
    const int tig  = lane & 3;
    const int bh = blockIdx.y;
    const int b  = bh >> 4;
    const int h  = bh & 15;
    const int q0 = blockIdx.x * 128;

    float* Ah = attn + ((size_t)bh*Sn + q0) * Sn;
    const __nv_bfloat16* vt0 = g_vt0 + (size_t)bh * DKn * Sn;
    const __nv_bfloat16* vt1 = g_vt1 + (size_t)bh * DKn * Sn;

    const int len = length[b];
    int kmax = (len + 31) & ~31;
    if (kmax > Sn) kmax = Sn;

    if (tid < 128) {
        const float* pp = &g_part[((size_t)bh*Sn + q0 + tid)*8];
        float4 p0 = *(const float4*)pp;
        float4 p1 = *(const float4*)(pp + 4);
        float s = p0.x + p0.y + p0.z + p0.w + p1.x + p1.y + p1.z + p1.w;
        invS[tid] = 1.0f / (s + 1e-8f);
    }

    float4 acc[2];
    acc[0] = make_float4(0.f, 0.f, 0.f, 0.f);
    acc[1] = make_float4(0.f, 0.f, 0.f, 0.f);
    // full 8-n-tile accumulators (one warp covers 16 q rows x 64 dk)
    float4 accB[8];
#pragma unroll
    for (int nt = 0; nt < 8; nt++) accB[nt] = make_float4(0.f, 0.f, 0.f, 0.f);

    for (int kc = 0; kc < kmax; kc += 32) {
        float4 av[4];
        float iv[4];
#pragma unroll
        for (int j = 0; j < 4; j++) {
            int f = tid + j*256;
            int row = f >> 3, cc = f & 7;
            av[j] = *(const float4*)(Ah + (size_t)row*Sn + kc + cc*4);
        }
        uint2 bv0[2], bv1[2];
#pragma unroll
        for (int j = 0; j < 2; j++) {
            int g = tid + j*256;
            int row = g >> 3, cc = g & 7;
            bv0[j] = *(const uint2*)(vt0 + (size_t)row*Sn + kc + cc*4);
            bv1[j] = *(const uint2*)(vt1 + (size_t)row*Sn + kc + cc*4);
        }
        __syncthreads();
#pragma unroll
        for (int j = 0; j < 4; j++) {
            int f = tid + j*256;
            int row = f >> 3, cc = f & 7;
            iv[j] = invS[row];
            float4 vv = av[j];
            vv.x *= iv[j]; vv.y *= iv[j]; vv.z *= iv[j]; vv.w *= iv[j];
            *(float4*)(Ah + (size_t)row*Sn + kc + cc*4) = vv;
            __nv_bfloat16 h0,l0,h1,l1,h2,l2,h3,l3;
            bsplit(vv.x,h0,l0); bsplit(vv.y,h1,l1); bsplit(vv.z,h2,l2); bsplit(vv.w,h3,l3);
            int wo = row*SA + cc*2;
            As0[wo]   = packbf(h0,h1); As0[wo+1] = packbf(h2,h3);
            As1[wo]   = packbf(l0,l1); As1[wo+1] = packbf(l2,l3);
        }
#pragma unroll
        for (int j = 0; j < 2; j++) {
            int g = tid + j*256;
            int row = g >> 3, cc = g & 7;
            int wo = row*SA + cc*2;
            *(uint2*)&Bs0[wo] = bv0[j];
            *(uint2*)&Bs1[wo] = bv1[j];
        }
        __syncthreads();
#pragma unroll
        for (int s = 0; s < 2; s++) {
            uint32_t af0[4], af1[4];
            int base = (wid*16 + gid)*SA + s*8 + tig;
            af0[0] = As0[base];        af0[1] = As0[base + 8*SA];
            af0[2] = As0[base + 4];    af0[3] = As0[base + 8*SA + 4];
            af1[0] = As1[base];        af1[1] = As1[base + 8*SA];
            af1[2] = As1[base + 4];    af1[3] = As1[base + 8*SA + 4];
#pragma unroll
            for (int nt = 0; nt < 8; nt++) {
                int nb = (nt*8 + gid)*SA + s*8 + tig;
                uint32_t b00 = Bs0[nb], b01 = Bs0[nb + 4];
                uint32_t b10 = Bs1[nb], b11 = Bs1[nb + 4];
                mma_bf16(accB[nt], af0, b00, b01);   // a0*v0
                mma_bf16(accB[nt], af0, b10, b11);   // a0*v1
                mma_bf16(accB[nt], af1, b00, b01);   // a1*v0
            }
        }
        __syncthreads();
    }

    int sa = q0 + wid*16 + gid;
    int sb = sa + 8;
#pragma unroll
    for (int nt = 0; nt < 8; nt++) {
        int dk = nt*8 + tig*2;
        *(float2*)&ctx[((size_t)(b*Sn + sa))*Dn + h*DKn + dk] = make_float2(accB[nt].x, accB[nt].y);
        *(float2*)&ctx[((size_t)(b*Sn + sb))*Dn + h*DKn + dk] = make_float2(accB[nt].z, accB[nt].w);
    }
}

// ---------------------------------------------------------------------------
extern "C" void kernel_launch(void* const* d_in, const int* in_sizes, int n_in,
                              void* d_out, int out_size)
{
    const float* Q   = (const float*)d_in[0];
    const float* Wq  = (const float*)d_in[1];
    const float* bq  = (const float*)d_in[2];
    const float* Wk  = (const float*)d_in[3];
    const float* bk  = (const float*)d_in[4];
    const float* Wv  = (const float*)d_in[5];
    const float* bv  = (const float*)d_in[6];
    const int*   len = (const int*)d_in[7];

    float* ctx = (float*)d_out;
    float* attn;
    if ((size_t)out_size >= (size_t)CTX_ELEMS + ATT_ELEMS) {
        attn = ctx + CTX_ELEMS;   // tuple output: [context | attn]
    } else {
        void* p = nullptr;
        cudaGetSymbolAddress(&p, g_attn_fallback);
        attn = (float*)p;
    }

    // 0) int8 two-digit quantization of X and W (per-row scales)
    prep_xq_kernel<<<dim3(Mtot), 256>>>(Q);
    prep_wq_kernel<<<dim3(3*Dn), 256>>>(Wq, Wk, Wv);
    // 1) QKV projections via int8 mma (z = 0:q, 1:k, 2:v)
    qkv_i8_kernel<<<dim3(Dn/64, Mtot/128, 3), 256>>>(bq, bk, bv);
    // 1b) V^T bf16 splits
    vtrans_kernel<<<dim3(Sn/64, BH), 256>>>();
    // 2) scores (bf16 mma): exp+mask+partials, masked tiles short-circuit
    scores_mma_kernel<<<dim3(Sn/128, Sn/128, BH), 256>>>(len, attn);
    // 3) context = (E @ V) * inv (bf16 mma; normalizes attn in place)
    av_mma_kernel<<<dim3(Sn/128, BH), 256>>>(len, attn, ctx);
}

// round 9
// speedup vs baseline: 2.0248x; 1.9442x over previous
#include <cuda_runtime.h>
#include <cuda_bf16.h>
#include <math.h>
#include <stdint.h>

#define Bn   32
#define Sn   512
#define Dn   1024
#define Hn   16
#define DKn  64
#define BH   (Bn*Hn)                 // 512
#define Mtot (Bn*Sn)                 // 16384
#define CTX_ELEMS (Bn*Sn*Dn)         // 16,777,216
#define ATT_ELEMS ((size_t)Bn*Hn*Sn*Sn) // 134,217,728

// Scratch (allocation-free per harness rules)
__device__ float g_v[CTX_ELEMS];
__device__ float g_part[(size_t)BH*Sn*8];
__device__ float g_attn_fallback[ATT_ELEMS];
// bf16 hi/lo splits
__device__ __nv_bfloat16 g_xb0[CTX_ELEMS];
__device__ __nv_bfloat16 g_xb1[CTX_ELEMS];
__device__ __nv_bfloat16 g_wb0[3*Dn*Dn];
__device__ __nv_bfloat16 g_wb1[3*Dn*Dn];
__device__ __nv_bfloat16 g_qb0[CTX_ELEMS];
__device__ __nv_bfloat16 g_qb1[CTX_ELEMS];
__device__ __nv_bfloat16 g_kb0[CTX_ELEMS];
__device__ __nv_bfloat16 g_kb1[CTX_ELEMS];
__device__ __nv_bfloat16 g_vt0[CTX_ELEMS];   // V^T: [bh][dk=64][s=512]
__device__ __nv_bfloat16 g_vt1[CTX_ELEMS];

// ---------------- mma.sync bf16 (non-'a' tensor path, works on sm_103) -----
__device__ __forceinline__ void mma_bf16(float4& d, const uint32_t* a,
                                         uint32_t b0, uint32_t b1) {
    asm volatile(
        "mma.sync.aligned.m16n8k16.row.col.f32.bf16.bf16.f32 "
        "{%0,%1,%2,%3},{%4,%5,%6,%7},{%8,%9},{%0,%1,%2,%3};"
        : "+f"(d.x), "+f"(d.y), "+f"(d.z), "+f"(d.w)
        : "r"(a[0]), "r"(a[1]), "r"(a[2]), "r"(a[3]), "r"(b0), "r"(b1));
}

__device__ __forceinline__ void bsplit(float v, __nv_bfloat16& h, __nv_bfloat16& l) {
    h = __float2bfloat16(v);
    l = __float2bfloat16(v - __bfloat162float(h));
}
__device__ __forceinline__ uint32_t packbf(__nv_bfloat16 a, __nv_bfloat16 b) {
    __nv_bfloat162 t(a, b);
    return *(uint32_t*)&t;
}

// ---------------------------------------------------------------------------
// prep: bf16 hi/lo splits of X and the 3 weight matrices
// ---------------------------------------------------------------------------
__global__ __launch_bounds__(256) void prep_x_kernel(const float* __restrict__ X)
{
    size_t i = (size_t)blockIdx.x * 256 + threadIdx.x;
    float4 v = ((const float4*)X)[i];
    float f[4] = {v.x, v.y, v.z, v.w};
    __nv_bfloat16 b0[4], b1[4];
#pragma unroll
    for (int k = 0; k < 4; k++) bsplit(f[k], b0[k], b1[k]);
    ((uint32_t*)g_xb0)[i*2]   = packbf(b0[0], b0[1]);
    ((uint32_t*)g_xb0)[i*2+1] = packbf(b0[2], b0[3]);
    ((uint32_t*)g_xb1)[i*2]   = packbf(b1[0], b1[1]);
    ((uint32_t*)g_xb1)[i*2+1] = packbf(b1[2], b1[3]);
}

__global__ __launch_bounds__(256) void prep_w_kernel(
    const float* __restrict__ Wq, const float* __restrict__ Wk, const float* __restrict__ Wv)
{
    size_t i = (size_t)blockIdx.x * 256 + threadIdx.x;
    int z = (int)(i >> 18);
    const float* src = (z == 0) ? Wq : (z == 1) ? Wk : Wv;
    float4 v = ((const float4*)src)[i & 262143];
    float f[4] = {v.x, v.y, v.z, v.w};
    __nv_bfloat16 b0[4], b1[4];
#pragma unroll
    for (int k = 0; k < 4; k++) bsplit(f[k], b0[k], b1[k]);
    ((uint32_t*)g_wb0)[i*2]   = packbf(b0[0], b0[1]);
    ((uint32_t*)g_wb0)[i*2+1] = packbf(b0[2], b0[3]);
    ((uint32_t*)g_wb1)[i*2]   = packbf(b1[0], b1[1]);
    ((uint32_t*)g_wb1)[i*2+1] = packbf(b1[2], b1[3]);
}

// ---------------------------------------------------------------------------
// QKV projection via mma.sync bf16x3: C = X @ W^T + bias
// K/V tiles whose batch-local row start >= length[b] are dead work: their
// outputs are never read (scores skips those k-tiles; av bounds its K loop).
// Early-exit those CTAs. Unwritten scratch stays zero -> safe.
// ---------------------------------------------------------------------------
#define SA 20   // smem row stride in words

__global__ __launch_bounds__(256, 2) void qkv_mma_kernel(
    const float* __restrict__ bq, const float* __restrict__ bk, const float* __restrict__ bv,
    const int* __restrict__ length)
{
    __shared__ uint32_t As[2][128*SA];
    __shared__ uint32_t Bs[2][128*SA];

    const int tid  = threadIdx.x;
    const int wid  = tid >> 5;
    const int lane = tid & 31;
    const int gid  = lane >> 2;
    const int tig  = lane & 3;
    const int wm   = wid >> 1;
    const int wn   = wid & 1;
    const int z    = blockIdx.z;
    const int bm   = blockIdx.y * 128;
    const int bn   = blockIdx.x * 128;

    // dead-tile skip for K and V projections
    if (z >= 1) {
        if ((bm & 511) >= length[bm >> 9]) return;
    }

    const size_t zoff = (size_t)z * Dn * Dn;
    const __nv_bfloat16* w0p = g_wb0 + zoff;
    const __nv_bfloat16* w1p = g_wb1 + zoff;

    const int r0 = tid >> 3;
    const int c4 = tid & 7;

    float4 acc[2][8];
#pragma unroll
    for (int mt = 0; mt < 2; mt++)
#pragma unroll
        for (int nt = 0; nt < 8; nt++) acc[mt][nt] = make_float4(0.f, 0.f, 0.f, 0.f);

    uint2 areg[4], breg[4];
    {
        const __nv_bfloat16* a = g_xb0 + (size_t)bm * Dn;
        const __nv_bfloat16* w = w0p   + (size_t)bn * Dn;
#pragma unroll
        for (int j = 0; j < 4; j++) {
            int row = r0 + j*32;
            areg[j] = *(const uint2*)(a + (size_t)row*Dn + c4*4);
            breg[j] = *(const uint2*)(w + (size_t)row*Dn + c4*4);
        }
#pragma unroll
        for (int j = 0; j < 4; j++) {
            int row = r0 + j*32;
            int wo = row*SA + c4*2;
            *(uint2*)&As[0][wo] = areg[j];
            *(uint2*)&Bs[0][wo] = breg[j];
        }
    }
    __syncthreads();

    for (int it = 0; it < 96; it++) {
        const int cur = it & 1;
        if (it + 1 < 96) {
            int p  = (it + 1) >> 5;
            int kc = ((it + 1) & 31) * 32;
            const __nv_bfloat16* a = ((p == 2) ? g_xb1 : g_xb0) + (size_t)bm * Dn + kc;
            const __nv_bfloat16* w = ((p == 1) ? w1p  : w0p  ) + (size_t)bn * Dn + kc;
#pragma unroll
            for (int j = 0; j < 4; j++) {
                int row = r0 + j*32;
                areg[j] = *(const uint2*)(a + (size_t)row*Dn + c4*4);
                breg[j] = *(const uint2*)(w + (size_t)row*Dn + c4*4);
            }
        }
#pragma unroll
        for (int s = 0; s < 2; s++) {
            uint32_t af[2][4];
#pragma unroll
            for (int mt = 0; mt < 2; mt++) {
                int base = (wm*32 + mt*16 + gid)*SA + s*8 + tig;
                af[mt][0] = As[cur][base];
                af[mt][1] = As[cur][base + 8*SA];
                af[mt][2] = As[cur][base + 4];
                af[mt][3] = As[cur][base + 8*SA + 4];
            }
#pragma unroll
            for (int nt = 0; nt < 8; nt++) {
                int nb = (wn*64 + nt*8 + gid)*SA + s*8 + tig;
                uint32_t b0 = Bs[cur][nb];
                uint32_t b1 = Bs[cur][nb + 4];
                mma_bf16(acc[0][nt], af[0], b0, b1);
                mma_bf16(acc[1][nt], af[1], b0, b1);
            }
        }
        if (it + 1 < 96) {
            const int nxt = (it + 1) & 1;
#pragma unroll
            for (int j = 0; j < 4; j++) {
                int row = r0 + j*32;
                int wo = row*SA + c4*2;
                *(uint2*)&As[nxt][wo] = areg[j];
                *(uint2*)&Bs[nxt][wo] = breg[j];
            }
            __syncthreads();
        }
    }

    const float* bias = (z == 0) ? bq : (z == 1) ? bk : bv;
    if (z == 2) {
#pragma unroll
        for (int mt = 0; mt < 2; mt++) {
            int rowa = bm + wm*32 + mt*16 + gid;
            int rowb = rowa + 8;
            int ba = rowa >> 9, sa = rowa & 511;
            int bb2 = rowb >> 9, sb = rowb & 511;
#pragma unroll
            for (int nt = 0; nt < 8; nt++) {
                int feat = bn + wn*64 + nt*8 + tig*2;
                int h = feat >> 6, dk = feat & 63;
                float2 bv2 = *(const float2*)&bias[feat];
                float2 v0 = make_float2(acc[mt][nt].x + bv2.x, acc[mt][nt].y + bv2.y);
                float2 v1 = make_float2(acc[mt][nt].z + bv2.x, acc[mt][nt].w + bv2.y);
                *(float2*)&g_v[((size_t)((ba *Hn + h)*Sn + sa))*DKn + dk] = v0;
                *(float2*)&g_v[((size_t)((bb2*Hn + h)*Sn + sb))*DKn + dk] = v1;
            }
        }
    } else {
        __nv_bfloat16* o0 = (z == 0) ? g_qb0 : g_kb0;
        __nv_bfloat16* o1 = (z == 0) ? g_qb1 : g_kb1;
#pragma unroll
        for (int mt = 0; mt < 2; mt++) {
            int rowa = bm + wm*32 + mt*16 + gid;
            int rowb = rowa + 8;
            int ba = rowa >> 9, sa = rowa & 511;
            int bb2 = rowb >> 9, sb = rowb & 511;
#pragma unroll
            for (int nt = 0; nt < 8; nt++) {
                int feat = bn + wn*64 + nt*8 + tig*2;
                int h = feat >> 6, dk = feat & 63;
                float2 bv2 = *(const float2*)&bias[feat];
                float vx = acc[mt][nt].x + bv2.x, vy = acc[mt][nt].y + bv2.y;
                float vz = acc[mt][nt].z + bv2.x, vw = acc[mt][nt].w + bv2.y;
                __nv_bfloat16 hx,lx,hy,ly,hz,lz,hw,lw;
                bsplit(vx,hx,lx); bsplit(vy,hy,ly); bsplit(vz,hz,lz); bsplit(vw,hw,lw);
                size_t ia = ((size_t)((ba *Hn + h)*Sn + sa))*DKn + dk;
                size_t ib = ((size_t)((bb2*Hn + h)*Sn + sb))*DKn + dk;
                *(uint32_t*)&o0[ia] = packbf(hx,hy);
                *(uint32_t*)&o1[ia] = packbf(lx,ly);
                *(uint32_t*)&o0[ib] = packbf(hz,hw);
                *(uint32_t*)&o1[ib] = packbf(lz,lw);
            }
        }
    }
}

// ---------------------------------------------------------------------------
// vtrans: g_v fp32 [bh][s][64] -> bf16 hi/lo V^T [bh][64][512]
// Tiles beyond roundup32(length[b]) are never read by av: skip.
// ---------------------------------------------------------------------------
__global__ __launch_bounds__(256) void vtrans_kernel(const int* __restrict__ length)
{
    const int bh = blockIdx.y;
    const int s0 = blockIdx.x * 64;
    {
        int len = length[bh >> 4];
        int kmax = (len + 31) & ~31; if (kmax > Sn) kmax = Sn;
        if (s0 >= kmax) return;
    }
    __shared__ float T[64][65];
    const int tid = threadIdx.x;
#pragma unroll
    for (int j = 0; j < 4; j++) {
        int f = tid + j*256;
        int row = f >> 4, cc = (f & 15) * 4;
        float4 v = *(const float4*)&g_v[((size_t)bh*Sn + s0 + row)*DKn + cc];
        T[row][cc] = v.x; T[row][cc+1] = v.y; T[row][cc+2] = v.z; T[row][cc+3] = v.w;
    }
    __syncthreads();
#pragma unroll
    for (int j = 0; j < 8; j++) {
        int g = tid + j*256;
        int dk = g >> 5, sc = (g & 31) * 2;
        float va = T[sc][dk], vb = T[sc+1][dk];
        __nv_bfloat16 ha,la,hb,lb;
        bsplit(va,ha,la); bsplit(vb,hb,lb);
        size_t idx = ((size_t)bh*DKn + dk)*Sn + s0 + sc;
        *(uint32_t*)&g_vt0[idx] = packbf(ha,hb);
        *(uint32_t*)&g_vt1[idx] = packbf(la,lb);
    }
}

// ---------------------------------------------------------------------------
// scores via mma: E[q][k] = exp((q·k)/8)*mask, 128x128 tile per block.
// Fully-masked tiles (k0 >= length[b]) short-circuit to a zero-fill.
// ---------------------------------------------------------------------------
__global__ __launch_bounds__(256, 2) void scores_mma_kernel(
    const int* __restrict__ length, float* __restrict__ attn)
{
    __shared__ uint32_t As[2][128*SA];
    __shared__ uint32_t Bs[2][128*SA];

    const int tid  = threadIdx.x;
    const int wid  = tid >> 5;
    const int lane = tid & 31;
    const int gid  = lane >> 2;
    const int tig  = lane & 3;
    const int wm   = wid >> 1;
    const int wn   = wid & 1;
    const int bh = blockIdx.z;
    const int b  = bh >> 4;
    const int q0 = blockIdx.y * 128;
    const int k0 = blockIdx.x * 128;

    const int len = length[b];

    if (k0 >= len) {
        float4 z4 = make_float4(0.f, 0.f, 0.f, 0.f);
#pragma unroll
        for (int j = 0; j < 16; j++) {
            int f = tid + j*256;
            int row = f >> 5, cc = (f & 31) * 4;
            *(float4*)&attn[((size_t)bh*Sn + q0 + row)*Sn + k0 + cc] = z4;
        }
        if (tid < 128) {
            size_t pb = ((size_t)bh*Sn + q0 + tid)*8 + blockIdx.x*2;
            g_part[pb]     = 0.f;
            g_part[pb + 1] = 0.f;
        }
        return;
    }

    const int r0 = tid >> 3;
    const int c4 = tid & 7;

    const __nv_bfloat16* qs[2] = { g_qb0 + ((size_t)bh*Sn + q0)*DKn,
                                   g_qb1 + ((size_t)bh*Sn + q0)*DKn };
    const __nv_bfloat16* ks[2] = { g_kb0 + ((size_t)bh*Sn + k0)*DKn,
                                   g_kb1 + ((size_t)bh*Sn + k0)*DKn };
    const int pa[3] = {0, 0, 1};
    const int pb3[3] = {0, 1, 0};

    float4 acc[2][8];
#pragma unroll
    for (int mt = 0; mt < 2; mt++)
#pragma unroll
        for (int nt = 0; nt < 8; nt++) acc[mt][nt] = make_float4(0.f, 0.f, 0.f, 0.f);

    uint2 areg[4], breg[4];
    {
#pragma unroll
        for (int j = 0; j < 4; j++) {
            int row = r0 + j*32;
            areg[j] = *(const uint2*)(qs[0] + (size_t)row*DKn + c4*4);
            breg[j] = *(const uint2*)(ks[0] + (size_t)row*DKn + c4*4);
        }
#pragma unroll
        for (int j = 0; j < 4; j++) {
            int row = r0 + j*32;
            int wo = row*SA + c4*2;
            *(uint2*)&As[0][wo] = areg[j];
            *(uint2*)&Bs[0][wo] = breg[j];
        }
    }
    __syncthreads();

    for (int it = 0; it < 6; it++) {
        const int cur = it & 1;
        if (it + 1 < 6) {
            int p  = (it + 1) >> 1;
            int kc = ((it + 1) & 1) * 32;
            const __nv_bfloat16* a = qs[pa[p]] + kc;
            const __nv_bfloat16* w = ks[pb3[p]] + kc;
#pragma unroll
            for (int j = 0; j < 4; j++) {
                int row = r0 + j*32;
                areg[j] = *(const uint2*)(a + (size_t)row*DKn + c4*4);
                breg[j] = *(const uint2*)(w + (size_t)row*DKn + c4*4);
            }
        }
#pragma unroll
        for (int s = 0; s < 2; s++) {
            uint32_t af[2][4];
#pragma unroll
            for (int mt = 0; mt < 2; mt++) {
                int base = (wm*32 + mt*16 + gid)*SA + s*8 + tig;
                af[mt][0] = As[cur][base];
                af[mt][1] = As[cur][base + 8*SA];
                af[mt][2] = As[cur][base + 4];
                af[mt][3] = As[cur][base + 8*SA + 4];
            }
#pragma unroll
            for (int nt = 0; nt < 8; nt++) {
                int nb = (wn*64 + nt*8 + gid)*SA + s*8 + tig;
                uint32_t b0 = Bs[cur][nb];
                uint32_t b1 = Bs[cur][nb + 4];
                mma_bf16(acc[0][nt], af[0], b0, b1);
                mma_bf16(acc[1][nt], af[1], b0, b1);
            }
        }
        if (it + 1 < 6) {
            const int nxt = (it + 1) & 1;
#pragma unroll
            for (int j = 0; j < 4; j++) {
                int row = r0 + j*32;
                int wo = row*SA + c4*2;
                *(uint2*)&As[nxt][wo] = areg[j];
                *(uint2*)&Bs[nxt][wo] = breg[j];
            }
            __syncthreads();
        }
    }

#pragma unroll
    for (int mt = 0; mt < 2; mt++) {
        int sa = q0 + wm*32 + mt*16 + gid;
        int sb = sa + 8;
        float rpa = 0.f, rpb = 0.f;
#pragma unroll
        for (int nt = 0; nt < 8; nt++) {
            int kc0 = k0 + wn*64 + nt*8 + tig*2;
            float4 a = acc[mt][nt];
            float ex = (kc0   < len) ? expf(a.x * 0.125f) : 0.f;
            float ey = (kc0+1 < len) ? expf(a.y * 0.125f) : 0.f;
            float ez = (kc0   < len) ? expf(a.z * 0.125f) : 0.f;
            float ew = (kc0+1 < len) ? expf(a.w * 0.125f) : 0.f;
            *(float2*)&attn[((size_t)bh*Sn + sa)*Sn + kc0] = make_float2(ex, ey);
            *(float2*)&attn[((size_t)bh*Sn + sb)*Sn + kc0] = make_float2(ez, ew);
            rpa += ex + ey;
            rpb += ez + ew;
        }
        rpa += __shfl_xor_sync(0xffffffffu, rpa, 1);
        rpa += __shfl_xor_sync(0xffffffffu, rpa, 2);
        rpb += __shfl_xor_sync(0xffffffffu, rpb, 1);
        rpb += __shfl_xor_sync(0xffffffffu, rpb, 2);
        if (tig == 0) {
            g_part[((size_t)bh*Sn + sa)*8 + blockIdx.x*2 + wn] = rpa;
            g_part[((size_t)bh*Sn + sb)*8 + blockIdx.x*2 + wn] = rpb;
        }
    }
}

// ---------------------------------------------------------------------------
// av via mma: ctx = (E @ V) * inv. M=128 q, N=64 dk, K bounded by length[b].
// Normalizes attn in place. Row sums folded in from g_part.
// ---------------------------------------------------------------------------
__global__ __launch_bounds__(256, 2) void av_mma_kernel(
    const int* __restrict__ length, float* __restrict__ attn, float* __restrict__ ctx)
{
    __shared__ uint32_t As0[128*SA];
    __shared__ uint32_t As1[128*SA];
    __shared__ uint32_t Bs0[64*SA];
    __shared__ uint32_t Bs1[64*SA];
    __shared__ float invS[128];

    const int tid  = threadIdx.x;
    const int wid  = tid >> 5;
    const int lane = tid & 31;
    const int gid  = lane >> 2;
    const int tig  = lane & 3;
    const int bh = blockIdx.y;
    const int b  = bh >> 4;
    const int h  = bh & 15;
    const int q0 = blockIdx.x * 128;

    float* Ah = attn + ((size_t)bh*Sn + q0) * Sn;
    const __nv_bfloat16* vt0 = g_vt0 + (size_t)bh * DKn * Sn;
    const __nv_bfloat16* vt1 = g_vt1 + (size_t)bh * DKn * Sn;

    const int len = length[b];
    int kmax = (len + 31) & ~31;
    if (kmax > Sn) kmax = Sn;

    if (tid < 128) {
        const float* pp = &g_part[((size_t)bh*Sn + q0 + tid)*8];
        float4 p0 = *(const float4*)pp;
        float4 p1 = *(const float4*)(pp + 4);
        float s = p0.x + p0.y + p0.z + p0.w + p1.x + p1.y + p1.z + p1.w;
        invS[tid] = 1.0f / (s + 1e-8f);
    }

    float4 accB[8];
#pragma unroll
    for (int nt = 0; nt < 8; nt++) accB[nt] = make_float4(0.f, 0.f, 0.f, 0.f);

    for (int kc = 0; kc < kmax; kc += 32) {
        float4 av[4];
        float iv[4];
#pragma unroll
        for (int j = 0; j < 4; j++) {
            int f = tid + j*256;
            int row = f >> 3, cc = f & 7;
            av[j] = *(const float4*)(Ah + (size_t)row*Sn + kc + cc*4);
        }
        uint2 bv0[2], bv1[2];
#pragma unroll
        for (int j = 0; j < 2; j++) {
            int g = tid + j*256;
            int row = g >> 3, cc = g & 7;
            bv0[j] = *(const uint2*)(vt0 + (size_t)row*Sn + kc + cc*4);
            bv1[j] = *(const uint2*)(vt1 + (size_t)row*Sn + kc + cc*4);
        }
        __syncthreads();
#pragma unroll
        for (int j = 0; j < 4; j++) {
            int f = tid + j*256;
            int row = f >> 3, cc = f & 7;
            iv[j] = invS[row];
            float4 vv = av[j];
            vv.x *= iv[j]; vv.y *= iv[j]; vv.z *= iv[j]; vv.w *= iv[j];
            *(float4*)(Ah + (size_t)row*Sn + kc + cc*4) = vv;
            __nv_bfloat16 h0,l0,h1,l1,h2,l2,h3,l3;
            bsplit(vv.x,h0,l0); bsplit(vv.y,h1,l1); bsplit(vv.z,h2,l2); bsplit(vv.w,h3,l3);
            int wo = row*SA + cc*2;
            As0[wo]   = packbf(h0,h1); As0[wo+1] = packbf(h2,h3);
            As1[wo]   = packbf(l0,l1); As1[wo+1] = packbf(l2,l3);
        }
#pragma unroll
        for (int j = 0; j < 2; j++) {
            int g = tid + j*256;
            int row = g >> 3, cc = g & 7;
            int wo = row*SA + cc*2;
            *(uint2*)&Bs0[wo] = bv0[j];
            *(uint2*)&Bs1[wo] = bv1[j];
        }
        __syncthreads();
#pragma unroll
        for (int s = 0; s < 2; s++) {
            uint32_t af0[4], af1[4];
            int base = (wid*16 + gid)*SA + s*8 + tig;
            af0[0] = As0[base];        af0[1] = As0[base + 8*SA];
            af0[2] = As0[base + 4];    af0[3] = As0[base + 8*SA + 4];
            af1[0] = As1[base];        af1[1] = As1[base + 8*SA];
            af1[2] = As1[base + 4];    af1[3] = As1[base + 8*SA + 4];
#pragma unroll
            for (int nt = 0; nt < 8; nt++) {
                int nb = (nt*8 + gid)*SA + s*8 + tig;
                uint32_t b00 = Bs0[nb], b01 = Bs0[nb + 4];
                uint32_t b10 = Bs1[nb], b11 = Bs1[nb + 4];
                mma_bf16(accB[nt], af0, b00, b01);   // a0*v0
                mma_bf16(accB[nt], af0, b10, b11);   // a0*v1
                mma_bf16(accB[nt], af1, b00, b01);   // a1*v0
            }
        }
    }

    int sa = q0 + wid*16 + gid;
    int sb = sa + 8;
#pragma unroll
    for (int nt = 0; nt < 8; nt++) {
        int dk = nt*8 + tig*2;
        *(float2*)&ctx[((size_t)(b*Sn + sa))*Dn + h*DKn + dk] = make_float2(accB[nt].x, accB[nt].y);
        *(float2*)&ctx[((size_t)(b*Sn + sb))*Dn + h*DKn + dk] = make_float2(accB[nt].z, accB[nt].w);
    }
}

// ---------------------------------------------------------------------------
extern "C" void kernel_launch(void* const* d_in, const int* in_sizes, int n_in,
                              void* d_out, int out_size)
{
    const float* Q   = (const float*)d_in[0];
    const float* Wq  = (const float*)d_in[1];
    const float* bq  = (const float*)d_in[2];
    const float* Wk  = (const float*)d_in[3];
    const float* bk  = (const float*)d_in[4];
    const float* Wv  = (const float*)d_in[5];
    const float* bv  = (const float*)d_in[6];
    const int*   len = (const int*)d_in[7];

    float* ctx = (float*)d_out;
    float* attn;
    if ((size_t)out_size >= (size_t)CTX_ELEMS + ATT_ELEMS) {
        attn = ctx + CTX_ELEMS;   // tuple output: [context | attn]
    } else {
        void* p = nullptr;
        cudaGetSymbolAddress(&p, g_attn_fallback);
        attn = (float*)p;
    }

    // 0) bf16 hi/lo splits of inputs
    prep_x_kernel<<<dim3(CTX_ELEMS/4/256), 256>>>(Q);
    prep_w_kernel<<<dim3(3*Dn*Dn/4/256), 256>>>(Wq, Wk, Wv);
    // 1) QKV projections (tensor cores); dead K/V tiles skipped
    qkv_mma_kernel<<<dim3(Dn/128, Mtot/128, 3), 256>>>(bq, bk, bv, len);
    // 1b) V^T bf16 splits (tiles beyond length skipped)
    vtrans_kernel<<<dim3(Sn/64, BH), 256>>>(len);
    // 2) scores (tensor cores): exp+mask+partials, masked tiles short-circuit
    scores_mma_kernel<<<dim3(Sn/128, Sn/128, BH), 256>>>(len, attn);
    // 3) context = (E @ V) * inv (tensor cores; normalizes attn in place)
    av_mma_kernel<<<dim3(Sn/128, BH), 256>>>(len, attn, ctx);
}

// round 10
// speedup vs baseline: 2.0746x; 1.0246x over previous
#include <cuda_runtime.h>
#include <cuda_bf16.h>
#include <math.h>
#include <stdint.h>

#define Bn   32
#define Sn   512
#define Dn   1024
#define Hn   16
#define DKn  64
#define BH   (Bn*Hn)                 // 512
#define Mtot (Bn*Sn)                 // 16384
#define CTX_ELEMS (Bn*Sn*Dn)         // 16,777,216
#define ATT_ELEMS ((size_t)Bn*Hn*Sn*Sn) // 134,217,728

// Scratch (allocation-free per harness rules)
__device__ float g_v[CTX_ELEMS];
__device__ float g_part[(size_t)BH*Sn*8];
__device__ float g_attn_fallback[ATT_ELEMS];
// bf16 hi/lo splits
__device__ __nv_bfloat16 g_xb0[CTX_ELEMS];
__device__ __nv_bfloat16 g_xb1[CTX_ELEMS];
__device__ __nv_bfloat16 g_wb0[3*Dn*Dn];
__device__ __nv_bfloat16 g_wb1[3*Dn*Dn];
__device__ __nv_bfloat16 g_qb0[CTX_ELEMS];
__device__ __nv_bfloat16 g_qb1[CTX_ELEMS];
__device__ __nv_bfloat16 g_kb0[CTX_ELEMS];
__device__ __nv_bfloat16 g_kb1[CTX_ELEMS];
__device__ __nv_bfloat16 g_vt0[CTX_ELEMS];   // V^T: [bh][dk=64][s=512]
__device__ __nv_bfloat16 g_vt1[CTX_ELEMS];

// ---------------- mma.sync bf16 (non-'a' tensor path, works on sm_103) -----
__device__ __forceinline__ void mma_bf16(float4& d, const uint32_t* a,
                                         uint32_t b0, uint32_t b1) {
    asm volatile(
        "mma.sync.aligned.m16n8k16.row.col.f32.bf16.bf16.f32 "
        "{%0,%1,%2,%3},{%4,%5,%6,%7},{%8,%9},{%0,%1,%2,%3};"
        : "+f"(d.x), "+f"(d.y), "+f"(d.z), "+f"(d.w)
        : "r"(a[0]), "r"(a[1]), "r"(a[2]), "r"(a[3]), "r"(b0), "r"(b1));
}

__device__ __forceinline__ void bsplit(float v, __nv_bfloat16& h, __nv_bfloat16& l) {
    h = __float2bfloat16(v);
    l = __float2bfloat16(v - __bfloat162float(h));
}
__device__ __forceinline__ uint32_t packbf(__nv_bfloat16 a, __nv_bfloat16 b) {
    __nv_bfloat162 t(a, b);
    return *(uint32_t*)&t;
}

// ---------------------------------------------------------------------------
// prep: bf16 hi/lo splits of X and the 3 weight matrices (single kernel)
// ---------------------------------------------------------------------------
#define XF4 (CTX_ELEMS/4)            // 4,194,304 float4 in X
#define WF4 (3*Dn*Dn/4)              // 786,432 float4 in W

__global__ __launch_bounds__(256) void prep_kernel(
    const float* __restrict__ X,
    const float* __restrict__ Wq, const float* __restrict__ Wk, const float* __restrict__ Wv)
{
    size_t i = (size_t)blockIdx.x * 256 + threadIdx.x;
    const float* src;
    uint32_t *o0, *o1;
    size_t idx;
    if (i < XF4) {
        src = X; idx = i;
        o0 = (uint32_t*)g_xb0; o1 = (uint32_t*)g_xb1;
    } else {
        size_t j = i - XF4;
        if (j >= WF4) return;
        int z = (int)(j >> 18);
        src = (z == 0) ? Wq : (z == 1) ? Wk : Wv;
        idx = j & 262143;
        o0 = (uint32_t*)g_wb0 + (j >> 18 << 19);   // j block base *2 words
        o1 = (uint32_t*)g_wb1 + (j >> 18 << 19);
        o0 -= (size_t)(j >> 18) << 19;  // simplify: compute absolute below
        o1 -= (size_t)(j >> 18) << 19;
        // store at word offset j*2 within g_wb arrays
        float4 v = ((const float4*)src)[idx];
        float f[4] = {v.x, v.y, v.z, v.w};
        __nv_bfloat16 b0[4], b1[4];
#pragma unroll
        for (int k = 0; k < 4; k++) bsplit(f[k], b0[k], b1[k]);
        ((uint32_t*)g_wb0)[j*2]   = packbf(b0[0], b0[1]);
        ((uint32_t*)g_wb0)[j*2+1] = packbf(b0[2], b0[3]);
        ((uint32_t*)g_wb1)[j*2]   = packbf(b1[0], b1[1]);
        ((uint32_t*)g_wb1)[j*2+1] = packbf(b1[2], b1[3]);
        return;
    }
    float4 v = ((const float4*)src)[idx];
    float f[4] = {v.x, v.y, v.z, v.w};
    __nv_bfloat16 b0[4], b1[4];
#pragma unroll
    for (int k = 0; k < 4; k++) bsplit(f[k], b0[k], b1[k]);
    o0[idx*2]   = packbf(b0[0], b0[1]);
    o0[idx*2+1] = packbf(b0[2], b0[3]);
    o1[idx*2]   = packbf(b1[0], b1[1]);
    o1[idx*2+1] = packbf(b1[2], b1[3]);
}

// ---------------------------------------------------------------------------
// QKV projection via mma.sync bf16x3: C = X @ W^T + bias
// Dead K/V tiles (batch-local row start >= length[b]) early-exit.
// ---------------------------------------------------------------------------
#define SA 20   // smem row stride in words

__global__ __launch_bounds__(256, 2) void qkv_mma_kernel(
    const float* __restrict__ bq, const float* __restrict__ bk, const float* __restrict__ bv,
    const int* __restrict__ length)
{
    __shared__ uint32_t As[2][128*SA];
    __shared__ uint32_t Bs[2][128*SA];

    const int tid  = threadIdx.x;
    const int wid  = tid >> 5;
    const int lane = tid & 31;
    const int gid  = lane >> 2;
    const int tig  = lane & 3;
    const int wm   = wid >> 1;
    const int wn   = wid & 1;
    const int z    = blockIdx.z;
    const int bm   = blockIdx.y * 128;
    const int bn   = blockIdx.x * 128;

    if (z >= 1) {
        if ((bm & 511) >= length[bm >> 9]) return;
    }

    const size_t zoff = (size_t)z * Dn * Dn;
    const __nv_bfloat16* w0p = g_wb0 + zoff;
    const __nv_bfloat16* w1p = g_wb1 + zoff;

    const int r0 = tid >> 3;
    const int c4 = tid & 7;

    float4 acc[2][8];
#pragma unroll
    for (int mt = 0; mt < 2; mt++)
#pragma unroll
        for (int nt = 0; nt < 8; nt++) acc[mt][nt] = make_float4(0.f, 0.f, 0.f, 0.f);

    uint2 areg[4], breg[4];
    {
        const __nv_bfloat16* a = g_xb0 + (size_t)bm * Dn;
        const __nv_bfloat16* w = w0p   + (size_t)bn * Dn;
#pragma unroll
        for (int j = 0; j < 4; j++) {
            int row = r0 + j*32;
            areg[j] = *(const uint2*)(a + (size_t)row*Dn + c4*4);
            breg[j] = *(const uint2*)(w + (size_t)row*Dn + c4*4);
        }
#pragma unroll
        for (int j = 0; j < 4; j++) {
            int row = r0 + j*32;
            int wo = row*SA + c4*2;
            *(uint2*)&As[0][wo] = areg[j];
            *(uint2*)&Bs[0][wo] = breg[j];
        }
    }
    __syncthreads();

    for (int it = 0; it < 96; it++) {
        const int cur = it & 1;
        if (it + 1 < 96) {
            int p  = (it + 1) >> 5;
            int kc = ((it + 1) & 31) * 32;
            const __nv_bfloat16* a = ((p == 2) ? g_xb1 : g_xb0) + (size_t)bm * Dn + kc;
            const __nv_bfloat16* w = ((p == 1) ? w1p  : w0p  ) + (size_t)bn * Dn + kc;
#pragma unroll
            for (int j = 0; j < 4; j++) {
                int row = r0 + j*32;
                areg[j] = *(const uint2*)(a + (size_t)row*Dn + c4*4);
                breg[j] = *(const uint2*)(w + (size_t)row*Dn + c4*4);
            }
        }
#pragma unroll
        for (int s = 0; s < 2; s++) {
            uint32_t af[2][4];
#pragma unroll
            for (int mt = 0; mt < 2; mt++) {
                int base = (wm*32 + mt*16 + gid)*SA + s*8 + tig;
                af[mt][0] = As[cur][base];
                af[mt][1] = As[cur][base + 8*SA];
                af[mt][2] = As[cur][base + 4];
                af[mt][3] = As[cur][base + 8*SA + 4];
            }
#pragma unroll
            for (int nt = 0; nt < 8; nt++) {
                int nb = (wn*64 + nt*8 + gid)*SA + s*8 + tig;
                uint32_t b0 = Bs[cur][nb];
                uint32_t b1 = Bs[cur][nb + 4];
                mma_bf16(acc[0][nt], af[0], b0, b1);
                mma_bf16(acc[1][nt], af[1], b0, b1);
            }
        }
        if (it + 1 < 96) {
            const int nxt = (it + 1) & 1;
#pragma unroll
            for (int j = 0; j < 4; j++) {
                int row = r0 + j*32;
                int wo = row*SA + c4*2;
                *(uint2*)&As[nxt][wo] = areg[j];
                *(uint2*)&Bs[nxt][wo] = breg[j];
            }
            __syncthreads();
        }
    }

    const float* bias = (z == 0) ? bq : (z == 1) ? bk : bv;
    if (z == 2) {
#pragma unroll
        for (int mt = 0; mt < 2; mt++) {
            int rowa = bm + wm*32 + mt*16 + gid;
            int rowb = rowa + 8;
            int ba = rowa >> 9, sa = rowa & 511;
            int bb2 = rowb >> 9, sb = rowb & 511;
#pragma unroll
            for (int nt = 0; nt < 8; nt++) {
                int feat = bn + wn*64 + nt*8 + tig*2;
                int h = feat >> 6, dk = feat & 63;
                float2 bv2 = *(const float2*)&bias[feat];
                float2 v0 = make_float2(acc[mt][nt].x + bv2.x, acc[mt][nt].y + bv2.y);
                float2 v1 = make_float2(acc[mt][nt].z + bv2.x, acc[mt][nt].w + bv2.y);
                *(float2*)&g_v[((size_t)((ba *Hn + h)*Sn + sa))*DKn + dk] = v0;
                *(float2*)&g_v[((size_t)((bb2*Hn + h)*Sn + sb))*DKn + dk] = v1;
            }
        }
    } else {
        __nv_bfloat16* o0 = (z == 0) ? g_qb0 : g_kb0;
        __nv_bfloat16* o1 = (z == 0) ? g_qb1 : g_kb1;
#pragma unroll
        for (int mt = 0; mt < 2; mt++) {
            int rowa = bm + wm*32 + mt*16 + gid;
            int rowb = rowa + 8;
            int ba = rowa >> 9, sa = rowa & 511;
            int bb2 = rowb >> 9, sb = rowb & 511;
#pragma unroll
            for (int nt = 0; nt < 8; nt++) {
                int feat = bn + wn*64 + nt*8 + tig*2;
                int h = feat >> 6, dk = feat & 63;
                float2 bv2 = *(const float2*)&bias[feat];
                float vx = acc[mt][nt].x + bv2.x, vy = acc[mt][nt].y + bv2.y;
                float vz = acc[mt][nt].z + bv2.x, vw = acc[mt][nt].w + bv2.y;
                __nv_bfloat16 hx,lx,hy,ly,hz,lz,hw,lw;
                bsplit(vx,hx,lx); bsplit(vy,hy,ly); bsplit(vz,hz,lz); bsplit(vw,hw,lw);
                size_t ia = ((size_t)((ba *Hn + h)*Sn + sa))*DKn + dk;
                size_t ib = ((size_t)((bb2*Hn + h)*Sn + sb))*DKn + dk;
                *(uint32_t*)&o0[ia] = packbf(hx,hy);
                *(uint32_t*)&o1[ia] = packbf(lx,ly);
                *(uint32_t*)&o0[ib] = packbf(hz,hw);
                *(uint32_t*)&o1[ib] = packbf(lz,lw);
            }
        }
    }
}

// ---------------------------------------------------------------------------
// vtrans: g_v fp32 [bh][s][64] -> bf16 hi/lo V^T [bh][64][512]
// ---------------------------------------------------------------------------
__global__ __launch_bounds__(256) void vtrans_kernel(const int* __restrict__ length)
{
    const int bh = blockIdx.y;
    const int s0 = blockIdx.x * 64;
    {
        int len = length[bh >> 4];
        int kmax = (len + 31) & ~31; if (kmax > Sn) kmax = Sn;
        if (s0 >= kmax) return;
    }
    __shared__ float T[64][65];
    const int tid = threadIdx.x;
#pragma unroll
    for (int j = 0; j < 4; j++) {
        int f = tid + j*256;
        int row = f >> 4, cc = (f & 15) * 4;
        float4 v = *(const float4*)&g_v[((size_t)bh*Sn + s0 + row)*DKn + cc];
        T[row][cc] = v.x; T[row][cc+1] = v.y; T[row][cc+2] = v.z; T[row][cc+3] = v.w;
    }
    __syncthreads();
#pragma unroll
    for (int j = 0; j < 8; j++) {
        int g = tid + j*256;
        int dk = g >> 5, sc = (g & 31) * 2;
        float va = T[sc][dk], vb = T[sc+1][dk];
        __nv_bfloat16 ha,la,hb,lb;
        bsplit(va,ha,la); bsplit(vb,hb,lb);
        size_t idx = ((size_t)bh*DKn + dk)*Sn + s0 + sc;
        *(uint32_t*)&g_vt0[idx] = packbf(ha,hb);
        *(uint32_t*)&g_vt1[idx] = packbf(la,lb);
    }
}

// ---------------------------------------------------------------------------
// scores via mma: E[q][k] = __expf((q·k)/8)*mask, 128x128 tile per block.
// Fully-masked tiles short-circuit to zero-fill.
// ---------------------------------------------------------------------------
__global__ __launch_bounds__(256, 2) void scores_mma_kernel(
    const int* __restrict__ length, float* __restrict__ attn)
{
    __shared__ uint32_t As[2][128*SA];
    __shared__ uint32_t Bs[2][128*SA];

    const int tid  = threadIdx.x;
    const int wid  = tid >> 5;
    const int lane = tid & 31;
    const int gid  = lane >> 2;
    const int tig  = lane & 3;
    const int wm   = wid >> 1;
    const int wn   = wid & 1;
    const int bh = blockIdx.z;
    const int b  = bh >> 4;
    const int q0 = blockIdx.y * 128;
    const int k0 = blockIdx.x * 128;

    const int len = length[b];

    if (k0 >= len) {
        float4 z4 = make_float4(0.f, 0.f, 0.f, 0.f);
#pragma unroll
        for (int j = 0; j < 16; j++) {
            int f = tid + j*256;
            int row = f >> 5, cc = (f & 31) * 4;
            *(float4*)&attn[((size_t)bh*Sn + q0 + row)*Sn + k0 + cc] = z4;
        }
        if (tid < 128) {
            size_t pb = ((size_t)bh*Sn + q0 + tid)*8 + blockIdx.x*2;
            g_part[pb]     = 0.f;
            g_part[pb + 1] = 0.f;
        }
        return;
    }

    const int r0 = tid >> 3;
    const int c4 = tid & 7;

    const __nv_bfloat16* qs[2] = { g_qb0 + ((size_t)bh*Sn + q0)*DKn,
                                   g_qb1 + ((size_t)bh*Sn + q0)*DKn };
    const __nv_bfloat16* ks[2] = { g_kb0 + ((size_t)bh*Sn + k0)*DKn,
                                   g_kb1 + ((size_t)bh*Sn + k0)*DKn };
    const int pa[3] = {0, 0, 1};
    const int pb3[3] = {0, 1, 0};

    float4 acc[2][8];
#pragma unroll
    for (int mt = 0; mt < 2; mt++)
#pragma unroll
        for (int nt = 0; nt < 8; nt++) acc[mt][nt] = make_float4(0.f, 0.f, 0.f, 0.f);

    uint2 areg[4], breg[4];
    {
#pragma unroll
        for (int j = 0; j < 4; j++) {
            int row = r0 + j*32;
            areg[j] = *(const uint2*)(qs[0] + (size_t)row*DKn + c4*4);
            breg[j] = *(const uint2*)(ks[0] + (size_t)row*DKn + c4*4);
        }
#pragma unroll
        for (int j = 0; j < 4; j++) {
            int row = r0 + j*32;
            int wo = row*SA + c4*2;
            *(uint2*)&As[0][wo] = areg[j];
            *(uint2*)&Bs[0][wo] = breg[j];
        }
    }
    __syncthreads();

    for (int it = 0; it < 6; it++) {
        const int cur = it & 1;
        if (it + 1 < 6) {
            int p  = (it + 1) >> 1;
            int kc = ((it + 1) & 1) * 32;
            const __nv_bfloat16* a = qs[pa[p]] + kc;
            const __nv_bfloat16* w = ks[pb3[p]] + kc;
#pragma unroll
            for (int j = 0; j < 4; j++) {
                int row = r0 + j*32;
                areg[j] = *(const uint2*)(a + (size_t)row*DKn + c4*4);
                breg[j] = *(const uint2*)(w + (size_t)row*DKn + c4*4);
            }
        }
#pragma unroll
        for (int s = 0; s < 2; s++) {
            uint32_t af[2][4];
#pragma unroll
            for (int mt = 0; mt < 2; mt++) {
                int base = (wm*32 + mt*16 + gid)*SA + s*8 + tig;
                af[mt][0] = As[cur][base];
                af[mt][1] = As[cur][base + 8*SA];
                af[mt][2] = As[cur][base + 4];
                af[mt][3] = As[cur][base + 8*SA + 4];
            }
#pragma unroll
            for (int nt = 0; nt < 8; nt++) {
                int nb = (wn*64 + nt*8 + gid)*SA + s*8 + tig;
                uint32_t b0 = Bs[cur][nb];
                uint32_t b1 = Bs[cur][nb + 4];
                mma_bf16(acc[0][nt], af[0], b0, b1);
                mma_bf16(acc[1][nt], af[1], b0, b1);
            }
        }
        if (it + 1 < 6) {
            const int nxt = (it + 1) & 1;
#pragma unroll
            for (int j = 0; j < 4; j++) {
                int row = r0 + j*32;
                int wo = row*SA + c4*2;
                *(uint2*)&As[nxt][wo] = areg[j];
                *(uint2*)&Bs[nxt][wo] = breg[j];
            }
            __syncthreads();
        }
    }

#pragma unroll
    for (int mt = 0; mt < 2; mt++) {
        int sa = q0 + wm*32 + mt*16 + gid;
        int sb = sa + 8;
        float rpa = 0.f, rpb = 0.f;
#pragma unroll
        for (int nt = 0; nt < 8; nt++) {
            int kc0 = k0 + wn*64 + nt*8 + tig*2;
            float4 a = acc[mt][nt];
            float ex = (kc0   < len) ? __expf(a.x * 0.125f) : 0.f;
            float ey = (kc0+1 < len) ? __expf(a.y * 0.125f) : 0.f;
            float ez = (kc0   < len) ? __expf(a.z * 0.125f) : 0.f;
            float ew = (kc0+1 < len) ? __expf(a.w * 0.125f) : 0.f;
            *(float2*)&attn[((size_t)bh*Sn + sa)*Sn + kc0] = make_float2(ex, ey);
            *(float2*)&attn[((size_t)bh*Sn + sb)*Sn + kc0] = make_float2(ez, ew);
            rpa += ex + ey;
            rpb += ez + ew;
        }
        rpa += __shfl_xor_sync(0xffffffffu, rpa, 1);
        rpa += __shfl_xor_sync(0xffffffffu, rpa, 2);
        rpb += __shfl_xor_sync(0xffffffffu, rpb, 1);
        rpb += __shfl_xor_sync(0xffffffffu, rpb, 2);
        if (tig == 0) {
            g_part[((size_t)bh*Sn + sa)*8 + blockIdx.x*2 + wn] = rpa;
            g_part[((size_t)bh*Sn + sb)*8 + blockIdx.x*2 + wn] = rpb;
        }
    }
}

// ---------------------------------------------------------------------------
// av via mma: ctx = (E @ V) * inv. K bounded by length[b]. Normalizes attn
// in place. Register prefetch hides gmem latency behind mma.
// ---------------------------------------------------------------------------
__global__ __launch_bounds__(256, 2) void av_mma_kernel(
    const int* __restrict__ length, float* __restrict__ attn, float* __restrict__ ctx)
{
    __shared__ uint32_t As0[128*SA];
    __shared__ uint32_t As1[128*SA];
    __shared__ uint32_t Bs0[64*SA];
    __shared__ uint32_t Bs1[64*SA];
    __shared__ float invS[128];

    const int tid  = threadIdx.x;
    const int wid  = tid >> 5;
    const int lane = tid & 31;
    const int gid  = lane >> 2;
    const int tig  = lane & 3;
    const int bh = blockIdx.y;
    const int b  = bh >> 4;
    const int h  = bh & 15;
    const int q0 = blockIdx.x * 128;

    float* Ah = attn + ((size_t)bh*Sn + q0) * Sn;
    const __nv_bfloat16* vt0 = g_vt0 + (size_t)bh * DKn * Sn;
    const __nv_bfloat16* vt1 = g_vt1 + (size_t)bh * DKn * Sn;

    const int len = length[b];
    int kmax = (len + 31) & ~31;
    if (kmax > Sn) kmax = Sn;

    if (tid < 128) {
        const float* pp = &g_part[((size_t)bh*Sn + q0 + tid)*8];
        float4 p0 = *(const float4*)pp;
        float4 p1 = *(const float4*)(pp + 4);
        float s = p0.x + p0.y + p0.z + p0.w + p1.x + p1.y + p1.z + p1.w;
        invS[tid] = 1.0f / (s + 1e-8f);
    }

    float4 accB[8];
#pragma unroll
    for (int nt = 0; nt < 8; nt++) accB[nt] = make_float4(0.f, 0.f, 0.f, 0.f);

    const int arow = tid >> 3, ac = tid & 7;     // attn staging: 128 rows x 8 cols
    const int vrow = tid >> 3, vc = tid & 7;     // V^T staging (tid<512 covers 2 passes)

    // prefetch kc = 0
    float4 avr[4];
    uint2 b0r[2], b1r[2];
#pragma unroll
    for (int j = 0; j < 4; j++) {
        int f = tid + j*256;
        int row = f >> 3, cc = f & 7;
        avr[j] = *(const float4*)(Ah + (size_t)row*Sn + 0 + cc*4);
    }
#pragma unroll
    for (int j = 0; j < 2; j++) {
        int g = tid + j*256;
        int row = g >> 3, cc = g & 7;
        b0r[j] = *(const uint2*)(vt0 + (size_t)row*Sn + 0 + cc*4);
        b1r[j] = *(const uint2*)(vt1 + (size_t)row*Sn + 0 + cc*4);
    }

    for (int kc = 0; kc < kmax; kc += 32) {
        __syncthreads();   // prev mma done reading smem; invS ready on iter 0
#pragma unroll
        for (int j = 0; j < 4; j++) {
            int f = tid + j*256;
            int row = f >> 3, cc = f & 7;
            float iv = invS[row];
            float4 vv = avr[j];
            vv.x *= iv; vv.y *= iv; vv.z *= iv; vv.w *= iv;
            *(float4*)(Ah + (size_t)row*Sn + kc + cc*4) = vv;
            __nv_bfloat16 h0,l0,h1,l1,h2,l2,h3,l3;
            bsplit(vv.x,h0,l0); bsplit(vv.y,h1,l1); bsplit(vv.z,h2,l2); bsplit(vv.w,h3,l3);
            int wo = row*SA + cc*2;
            As0[wo]   = packbf(h0,h1); As0[wo+1] = packbf(h2,h3);
            As1[wo]   = packbf(l0,l1); As1[wo+1] = packbf(l2,l3);
        }
#pragma unroll
        for (int j = 0; j < 2; j++) {
            int g = tid + j*256;
            int row = g >> 3, cc = g & 7;
            int wo = row*SA + cc*2;
            *(uint2*)&Bs0[wo] = b0r[j];
            *(uint2*)&Bs1[wo] = b1r[j];
        }
        __syncthreads();

        // prefetch next chunk while mma runs
        if (kc + 32 < kmax) {
#pragma unroll
            for (int j = 0; j < 4; j++) {
                int f = tid + j*256;
                int row = f >> 3, cc = f & 7;
                avr[j] = *(const float4*)(Ah + (size_t)row*Sn + kc + 32 + cc*4);
            }
#pragma unroll
            for (int j = 0; j < 2; j++) {
                int g = tid + j*256;
                int row = g >> 3, cc = g & 7;
                b0r[j] = *(const uint2*)(vt0 + (size_t)row*Sn + kc + 32 + cc*4);
                b1r[j] = *(const uint2*)(vt1 + (size_t)row*Sn + kc + 32 + cc*4);
            }
        }

#pragma unroll
        for (int s = 0; s < 2; s++) {
            uint32_t af0[4], af1[4];
            int base = (wid*16 + gid)*SA + s*8 + tig;
            af0[0] = As0[base];        af0[1] = As0[base + 8*SA];
            af0[2] = As0[base + 4];    af0[3] = As0[base + 8*SA + 4];
            af1[0] = As1[base];        af1[1] = As1[base + 8*SA];
            af1[2] = As1[base + 4];    af1[3] = As1[base + 8*SA + 4];
#pragma unroll
            for (int nt = 0; nt < 8; nt++) {
                int nb = (nt*8 + gid)*SA + s*8 + tig;
                uint32_t b00 = Bs0[nb], b01 = Bs0[nb + 4];
                uint32_t b10 = Bs1[nb], b11 = Bs1[nb + 4];
                mma_bf16(accB[nt], af0, b00, b01);   // a0*v0
                mma_bf16(accB[nt], af0, b10, b11);   // a0*v1
                mma_bf16(accB[nt], af1, b00, b01);   // a1*v0
            }
        }
    }

    int sa = q0 + wid*16 + gid;
    int sb = sa + 8;
#pragma unroll
    for (int nt = 0; nt < 8; nt++) {
        int dk = nt*8 + tig*2;
        *(float2*)&ctx[((size_t)(b*Sn + sa))*Dn + h*DKn + dk] = make_float2(accB[nt].x, accB[nt].y);
        *(float2*)&ctx[((size_t)(b*Sn + sb))*Dn + h*DKn + dk] = make_float2(accB[nt].z, accB[nt].w);
    }
}

// ---------------------------------------------------------------------------
extern "C" void kernel_launch(void* const* d_in, const int* in_sizes, int n_in,
                              void* d_out, int out_size)
{
    const float* Q   = (const float*)d_in[0];
    const float* Wq  = (const float*)d_in[1];
    const float* bq  = (const float*)d_in[2];
    const float* Wk  = (const float*)d_in[3];
    const float* bk  = (const float*)d_in[4];
    const float* Wv  = (const float*)d_in[5];
    const float* bv  = (const float*)d_in[6];
    const int*   len = (const int*)d_in[7];

    float* ctx = (float*)d_out;
    float* attn;
    if ((size_t)out_size >= (size_t)CTX_ELEMS + ATT_ELEMS) {
        attn = ctx + CTX_ELEMS;   // tuple output: [context | attn]
    } else {
        void* p = nullptr;
        cudaGetSymbolAddress(&p, g_attn_fallback);
        attn = (float*)p;
    }

    // 0) bf16 hi/lo splits of inputs (single kernel)
    prep_kernel<<<dim3((XF4 + WF4 + 255)/256), 256>>>(Q, Wq, Wk, Wv);
    // 1) QKV projections (tensor cores); dead K/V tiles skipped
    qkv_mma_kernel<<<dim3(Dn/128, Mtot/128, 3), 256>>>(bq, bk, bv, len);
    // 1b) V^T bf16 splits (tiles beyond length skipped)
    vtrans_kernel<<<dim3(Sn/64, BH), 256>>>(len);
    // 2) scores (tensor cores): __expf+mask+partials, masked tiles short-circuit
    scores_mma_kernel<<<dim3(Sn/128, Sn/128, BH), 256>>>(len, attn);
    // 3) context = (E @ V) * inv (tensor cores; normalizes attn in place)
    av_mma_kernel<<<dim3(Sn/128, BH), 256>>>(len, attn, ctx);
}